// round 1
// baseline (speedup 1.0000x reference)
#include <cuda_runtime.h>
#include <math.h>
#include <float.h>

#define NROWS   131072
#define IN_DIM  56
#define H_DIM   512
#define D_DIM   256
#define K_CODES 1024
#define NQ      2

// ---------------- scratch (static device globals; no allocations) ----------
__device__ float g_h1[(size_t)NROWS * H_DIM];   // 268 MB
__device__ float g_h2[(size_t)NROWS * H_DIM];   // 268 MB
__device__ float g_z [(size_t)NROWS * D_DIM];   // 134 MB
__device__ float g_r [(size_t)NROWS * D_DIM];   // 134 MB
__device__ float g_q [(size_t)NROWS * D_DIM];   // 134 MB
__device__ int    g_idx[NROWS * NQ];
__device__ float  g_cn[NQ * K_CODES];
__device__ double g_vq_sum;
__device__ double g_enc_sum;

// ---------------- misc small kernels ---------------------------------------
__global__ void zero_acc_kernel() {
    g_vq_sum  = 0.0;
    g_enc_sum = 0.0;
}

// ||c||^2 per code row, one warp per row (2048 rows of 256 floats)
__global__ void cnorm_kernel(const float* __restrict__ cbs) {
    int gw   = (blockIdx.x * blockDim.x + threadIdx.x) >> 5;
    int lane = threadIdx.x & 31;
    if (gw < NQ * K_CODES) {
        const float* row = cbs + (size_t)gw * D_DIM;
        float s = 0.f;
        #pragma unroll
        for (int e = 0; e < D_DIM / 32; e++) {
            float v = row[lane + 32 * e];
            s += v * v;
        }
        #pragma unroll
        for (int o = 16; o > 0; o >>= 1) s += __shfl_xor_sync(0xffffffffu, s, o);
        if (lane == 0) g_cn[gw] = s;
    }
}

// ---------------- tiled fp32 GEMM: C = act(A @ B + bias) --------------------
// A[M,K] row-major, B[K,N] row-major. BM=128, BN=128, BK=8, 256 threads, 8x8/thread.
template<bool RELU>
__global__ __launch_bounds__(256)
void gemm128(const float* __restrict__ A, const float* __restrict__ B,
             const float* __restrict__ bias, float* __restrict__ C,
             int M, int N, int K)
{
    __shared__ float As[8][132];
    __shared__ float Bs[8][132];
    const int tx  = threadIdx.x;            // 0..15 (cols)
    const int ty  = threadIdx.y;            // 0..15 (rows)
    const int tid = ty * 16 + tx;
    const int m0  = blockIdx.y * 128;
    const int n0  = blockIdx.x * 128;

    float acc[8][8];
    #pragma unroll
    for (int i = 0; i < 8; i++)
        #pragma unroll
        for (int j = 0; j < 8; j++) acc[i][j] = 0.f;

    const int arow = tid >> 1, akk = (tid & 1) * 4;        // 128x8 A chunk
    const int bkk  = tid >> 5, bcol = (tid & 31) * 4;      // 8x128 B chunk

    for (int k0 = 0; k0 < K; k0 += 8) {
        float4 av = *(const float4*)(A + (size_t)(m0 + arow) * K + k0 + akk);
        As[akk + 0][arow] = av.x; As[akk + 1][arow] = av.y;
        As[akk + 2][arow] = av.z; As[akk + 3][arow] = av.w;

        float4 bv;
        if (n0 + bcol + 3 < N) {
            bv = *(const float4*)(B + (size_t)(k0 + bkk) * N + n0 + bcol);
        } else {
            float t0 = (n0 + bcol + 0 < N) ? B[(size_t)(k0 + bkk) * N + n0 + bcol + 0] : 0.f;
            float t1 = (n0 + bcol + 1 < N) ? B[(size_t)(k0 + bkk) * N + n0 + bcol + 1] : 0.f;
            float t2 = (n0 + bcol + 2 < N) ? B[(size_t)(k0 + bkk) * N + n0 + bcol + 2] : 0.f;
            float t3 = (n0 + bcol + 3 < N) ? B[(size_t)(k0 + bkk) * N + n0 + bcol + 3] : 0.f;
            bv = make_float4(t0, t1, t2, t3);
        }
        *(float4*)&Bs[bkk][bcol] = bv;
        __syncthreads();

        #pragma unroll
        for (int kk = 0; kk < 8; kk++) {
            float a[8], b[8];
            #pragma unroll
            for (int i = 0; i < 8; i++) a[i] = As[kk][ty * 8 + i];
            #pragma unroll
            for (int j = 0; j < 8; j++) b[j] = Bs[kk][tx * 8 + j];
            #pragma unroll
            for (int i = 0; i < 8; i++)
                #pragma unroll
                for (int j = 0; j < 8; j++) acc[i][j] += a[i] * b[j];
        }
        __syncthreads();
    }

    #pragma unroll
    for (int j = 0; j < 8; j++) {
        int n = n0 + tx * 8 + j;
        if (n < N) {
            float bb = bias[n];
            #pragma unroll
            for (int i = 0; i < 8; i++) {
                float v = acc[i][j] + bb;
                if (RELU) v = fmaxf(v, 0.f);
                C[(size_t)(m0 + ty * 8 + i) * N + n] = v;
            }
        }
    }
}

// ---------------- final decoder GEMM fused with L1 loss ---------------------
// BM=128, BN=64 (N=56), BK=8, TM=8, TN=4, 256 threads. Never writes dec_out.
__global__ __launch_bounds__(256)
void gemm_l1(const float* __restrict__ A, const float* __restrict__ B,
             const float* __restrict__ bias, const float* __restrict__ X,
             int M, int N, int K)
{
    __shared__ float As[8][132];
    __shared__ float Bs[8][68];
    const int tx  = threadIdx.x;            // 0..15
    const int ty  = threadIdx.y;            // 0..15
    const int tid = ty * 16 + tx;
    const int m0  = blockIdx.y * 128;
    const int n0  = blockIdx.x * 64;

    float acc[8][4];
    #pragma unroll
    for (int i = 0; i < 8; i++)
        #pragma unroll
        for (int j = 0; j < 4; j++) acc[i][j] = 0.f;

    const int arow = tid >> 1, akk = (tid & 1) * 4;
    const int bkk  = tid >> 4, bcol = (tid & 15) * 4;      // tid<128 loads B

    for (int k0 = 0; k0 < K; k0 += 8) {
        float4 av = *(const float4*)(A + (size_t)(m0 + arow) * K + k0 + akk);
        As[akk + 0][arow] = av.x; As[akk + 1][arow] = av.y;
        As[akk + 2][arow] = av.z; As[akk + 3][arow] = av.w;

        if (tid < 128) {
            float4 bv;
            if (n0 + bcol + 3 < N) {
                bv = *(const float4*)(B + (size_t)(k0 + bkk) * N + n0 + bcol);
            } else {
                float t0 = (n0 + bcol + 0 < N) ? B[(size_t)(k0 + bkk) * N + n0 + bcol + 0] : 0.f;
                float t1 = (n0 + bcol + 1 < N) ? B[(size_t)(k0 + bkk) * N + n0 + bcol + 1] : 0.f;
                float t2 = (n0 + bcol + 2 < N) ? B[(size_t)(k0 + bkk) * N + n0 + bcol + 2] : 0.f;
                float t3 = (n0 + bcol + 3 < N) ? B[(size_t)(k0 + bkk) * N + n0 + bcol + 3] : 0.f;
                bv = make_float4(t0, t1, t2, t3);
            }
            *(float4*)&Bs[bkk][bcol] = bv;
        }
        __syncthreads();

        #pragma unroll
        for (int kk = 0; kk < 8; kk++) {
            float a[8], b[4];
            #pragma unroll
            for (int i = 0; i < 8; i++) a[i] = As[kk][ty * 8 + i];
            #pragma unroll
            for (int j = 0; j < 4; j++) b[j] = Bs[kk][tx * 4 + j];
            #pragma unroll
            for (int i = 0; i < 8; i++)
                #pragma unroll
                for (int j = 0; j < 4; j++) acc[i][j] += a[i] * b[j];
        }
        __syncthreads();
    }

    float lsum = 0.f;
    #pragma unroll
    for (int j = 0; j < 4; j++) {
        int n = n0 + tx * 4 + j;
        if (n < N) {
            float bb = bias[n];
            #pragma unroll
            for (int i = 0; i < 8; i++) {
                float v = acc[i][j] + bb;
                lsum += fabsf(X[(size_t)(m0 + ty * 8 + i) * N + n] - v);
            }
        }
    }
    __shared__ float red[256];
    red[tid] = lsum;
    __syncthreads();
    for (int s = 128; s > 0; s >>= 1) {
        if (tid < s) red[tid] += red[tid + s];
        __syncthreads();
    }
    if (tid == 0) atomicAdd(&g_enc_sum, (double)red[0]);
}

// ---------------- VQ pass: distances (GEMM) + argmin + min-dist sum ---------
// Block handles 128 rows x all 1024 codes. score = ||c||^2 - 2 r.c ; distance
// adds ||r||^2 (accumulated from the A tile during the first column chunk).
__global__ __launch_bounds__(256)
void vq_pass(const float* __restrict__ R, const float* __restrict__ cb,
             int qoff, float* __restrict__ code_out)
{
    __shared__ float As[8][132];
    __shared__ float Bs[8][132];
    const int tx  = threadIdx.x;
    const int ty  = threadIdx.y;
    const int tid = ty * 16 + tx;
    const int m0  = blockIdx.x * 128;

    const float* cn = g_cn + qoff * K_CODES;

    float minv[8];
    int   mini[8];
    float rn[8];
    #pragma unroll
    for (int i = 0; i < 8; i++) { minv[i] = FLT_MAX; mini[i] = 0; rn[i] = 0.f; }

    const int arow = tid >> 1, akk = (tid & 1) * 4;
    const int bcolL = tid >> 1, bkkL = (tid & 1) * 4;

    for (int c0 = 0; c0 < K_CODES; c0 += 128) {
        float acc[8][8];
        #pragma unroll
        for (int i = 0; i < 8; i++)
            #pragma unroll
            for (int j = 0; j < 8; j++) acc[i][j] = 0.f;

        for (int k0 = 0; k0 < D_DIM; k0 += 8) {
            float4 av = *(const float4*)(R + (size_t)(m0 + arow) * D_DIM + k0 + akk);
            As[akk + 0][arow] = av.x; As[akk + 1][arow] = av.y;
            As[akk + 2][arow] = av.z; As[akk + 3][arow] = av.w;

            // codebook is [K_CODES, D] row-major: transpose-load
            float4 cv = *(const float4*)(cb + (size_t)(c0 + bcolL) * D_DIM + k0 + bkkL);
            Bs[bkkL + 0][bcolL] = cv.x; Bs[bkkL + 1][bcolL] = cv.y;
            Bs[bkkL + 2][bcolL] = cv.z; Bs[bkkL + 3][bcolL] = cv.w;
            __syncthreads();

            #pragma unroll
            for (int kk = 0; kk < 8; kk++) {
                float a[8], b[8];
                #pragma unroll
                for (int i = 0; i < 8; i++) a[i] = As[kk][ty * 8 + i];
                #pragma unroll
                for (int j = 0; j < 8; j++) b[j] = Bs[kk][tx * 8 + j];
                if (c0 == 0) {
                    #pragma unroll
                    for (int i = 0; i < 8; i++) rn[i] += a[i] * a[i];
                }
                #pragma unroll
                for (int i = 0; i < 8; i++)
                    #pragma unroll
                    for (int j = 0; j < 8; j++) acc[i][j] += a[i] * b[j];
            }
            __syncthreads();
        }

        #pragma unroll
        for (int j = 0; j < 8; j++) {
            int c = c0 + tx * 8 + j;
            float cnv = cn[c];
            #pragma unroll
            for (int i = 0; i < 8; i++) {
                float s = cnv - 2.f * acc[i][j];
                if (s < minv[i]) { minv[i] = s; mini[i] = c; }  // ascending c: first-min kept
            }
        }
    }

    // cross-thread (tx) argmin reduce per row + ||r||^2
    __shared__ float rv[128][17];
    __shared__ int   ri[128][17];
    __shared__ float rnrow[128];
    #pragma unroll
    for (int i = 0; i < 8; i++) {
        rv[ty * 8 + i][tx] = minv[i];
        ri[ty * 8 + i][tx] = mini[i];
    }
    if (tx == 0) {
        #pragma unroll
        for (int i = 0; i < 8; i++) rnrow[ty * 8 + i] = rn[i];
    }
    __syncthreads();

    float dist = 0.f;
    if (tid < 128) {
        float bv = rv[tid][0];
        int   bi = ri[tid][0];
        #pragma unroll
        for (int x = 1; x < 16; x++) {
            float v = rv[tid][x];
            int   c = ri[tid][x];
            if (v < bv || (v == bv && c < bi)) { bv = v; bi = c; }  // jnp.argmin tie-break
        }
        int n = m0 + tid;
        g_idx[n * NQ + qoff] = bi;
        code_out[(size_t)n * NQ] = (float)bi;   // code_out pre-offset by qoff
        dist = bv + rnrow[tid];                 // min squared distance
    }
    __shared__ float red[256];
    red[tid] = dist;
    __syncthreads();
    for (int s = 128; s > 0; s >>= 1) {
        if (tid < s) red[tid] += red[tid + s];
        __syncthreads();
    }
    if (tid == 0) atomicAdd(&g_vq_sum, (double)red[0]);
}

// ---------------- gathers ----------------------------------------------------
__global__ void gather_residual(const float* __restrict__ z, const float* __restrict__ cb0) {
    int n = blockIdx.x, e = threadIdx.x;   // 256 threads = D
    int c = g_idx[n * NQ + 0];
    float zv = z[(size_t)n * D_DIM + e];
    float cv = cb0[(size_t)c * D_DIM + e];
    g_r[(size_t)n * D_DIM + e] = zv - cv;
    g_q[(size_t)n * D_DIM + e] = cv;
}

__global__ void gather_add(const float* __restrict__ cb1) {
    int n = blockIdx.x, e = threadIdx.x;
    int c = g_idx[n * NQ + 1];
    g_q[(size_t)n * D_DIM + e] += cb1[(size_t)c * D_DIM + e];
}

// ---------------- finalize ---------------------------------------------------
__global__ void finalize_kernel(float* out, int write_loss) {
    if (write_loss) {
        double enc = g_enc_sum / ((double)NROWS * IN_DIM);
        double vq  = g_vq_sum  / ((double)NROWS * D_DIM);
        out[0] = (float)(enc + 5.0 * vq);
    }
}

// ---------------- launch -----------------------------------------------------
extern "C" void kernel_launch(void* const* d_in, const int* in_sizes, int n_in,
                              void* d_out, int out_size)
{
    const float* state = (const float*)d_in[0];
    const float* ew1 = (const float*)d_in[1];  const float* eb1 = (const float*)d_in[2];
    const float* ew2 = (const float*)d_in[3];  const float* eb2 = (const float*)d_in[4];
    const float* ew3 = (const float*)d_in[5];  const float* eb3 = (const float*)d_in[6];
    const float* dw1 = (const float*)d_in[7];  const float* db1 = (const float*)d_in[8];
    const float* dw2 = (const float*)d_in[9];  const float* db2 = (const float*)d_in[10];
    const float* dw3 = (const float*)d_in[11]; const float* db3 = (const float*)d_in[12];
    const float* cbs = (const float*)d_in[13];

    float* out = (float*)d_out;
    int code_base = out_size - NROWS * NQ;     // expected 1 (rep_loss first)
    if (code_base < 0) code_base = 0;
    float* codes = out + code_base;

    float *p_h1, *p_h2, *p_z, *p_r, *p_q;
    cudaGetSymbolAddress((void**)&p_h1, g_h1);
    cudaGetSymbolAddress((void**)&p_h2, g_h2);
    cudaGetSymbolAddress((void**)&p_z,  g_z);
    cudaGetSymbolAddress((void**)&p_r,  g_r);
    cudaGetSymbolAddress((void**)&p_q,  g_q);

    dim3 blk(16, 16);

    zero_acc_kernel<<<1, 1>>>();
    cnorm_kernel<<<(NQ * K_CODES * 32) / 256, 256>>>(cbs);

    // encoder
    gemm128<true ><<<dim3(H_DIM / 128, NROWS / 128), blk>>>(state, ew1, eb1, p_h1, NROWS, H_DIM, IN_DIM);
    gemm128<true ><<<dim3(H_DIM / 128, NROWS / 128), blk>>>(p_h1,  ew2, eb2, p_h2, NROWS, H_DIM, H_DIM);
    gemm128<false><<<dim3(D_DIM / 128, NROWS / 128), blk>>>(p_h2,  ew3, eb3, p_z,  NROWS, D_DIM, H_DIM);

    // residual VQ
    vq_pass<<<NROWS / 128, blk>>>(p_z, cbs, 0, codes + 0);
    gather_residual<<<NROWS, D_DIM>>>(p_z, cbs);
    vq_pass<<<NROWS / 128, blk>>>(p_r, cbs + (size_t)K_CODES * D_DIM, 1, codes + 1);
    gather_add<<<NROWS, D_DIM>>>(cbs + (size_t)K_CODES * D_DIM);

    // decoder (reuse h1/h2), last layer fused with L1 loss
    gemm128<true><<<dim3(H_DIM / 128, NROWS / 128), blk>>>(p_q,  dw1, db1, p_h1, NROWS, H_DIM, D_DIM);
    gemm128<true><<<dim3(H_DIM / 128, NROWS / 128), blk>>>(p_h1, dw2, db2, p_h2, NROWS, H_DIM, H_DIM);
    gemm_l1<<<dim3(1, NROWS / 128), blk>>>(p_h2, dw3, db3, state, NROWS, IN_DIM, H_DIM);

    finalize_kernel<<<1, 1>>>(out, code_base >= 1);
}

// round 12
// speedup vs baseline: 1.7698x; 1.7698x over previous
#include <cuda_runtime.h>
#include <math.h>
#include <float.h>

#define NROWS   131072
#define IN_DIM  56
#define H_DIM   512
#define D_DIM   256
#define K_CODES 1024
#define NQ      2
#define VQ_CAP  4096
#define VQ_MARGIN 2.0f

// ---------------- scratch (static device globals; no allocations) ----------
__device__ float g_h1[(size_t)NROWS * H_DIM];
__device__ float g_h2[(size_t)NROWS * H_DIM];
__device__ float g_z [(size_t)NROWS * D_DIM];
__device__ float g_r [(size_t)NROWS * D_DIM];
__device__ float g_q [(size_t)NROWS * D_DIM];
__device__ float g_dec[(size_t)NROWS * IN_DIM];
__device__ int    g_idx[NROWS * NQ];
__device__ float  g_cn[NQ * K_CODES];
__device__ double g_vq_sum;
__device__ double g_enc_sum;

// ---------------- helpers ----------------------------------------------------
__device__ __forceinline__ unsigned f2tf(float x) {
    unsigned u; asm("cvt.rna.tf32.f32 %0, %1;" : "=r"(u) : "f"(x)); return u;
}
__device__ __forceinline__ void mma_tf32(float c[4], const unsigned a[4], const unsigned b[2]) {
    asm volatile("mma.sync.aligned.m16n8k8.row.col.f32.tf32.tf32.f32 "
        "{%0,%1,%2,%3}, {%4,%5,%6,%7}, {%8,%9}, {%0,%1,%2,%3};"
        : "+f"(c[0]), "+f"(c[1]), "+f"(c[2]), "+f"(c[3])
        : "r"(a[0]), "r"(a[1]), "r"(a[2]), "r"(a[3]), "r"(b[0]), "r"(b[1]));
}
// order-preserving float<->uint maps (monotone, handles negatives)
__device__ __forceinline__ unsigned ordf(float f) {
    unsigned u = __float_as_uint(f);
    return (u >> 31) ? ~u : (u | 0x80000000u);
}
__device__ __forceinline__ float iordf(unsigned u) {
    return __uint_as_float((u >> 31) ? (u & 0x7FFFFFFFu) : ~u);
}

// ---------------- misc small kernels ---------------------------------------
__global__ void zero_acc_kernel() { g_vq_sum = 0.0; g_enc_sum = 0.0; }

__global__ void cnorm_kernel(const float* __restrict__ cbs) {
    int gw   = (blockIdx.x * blockDim.x + threadIdx.x) >> 5;
    int lane = threadIdx.x & 31;
    if (gw < NQ * K_CODES) {
        const float* row = cbs + (size_t)gw * D_DIM;
        float s = 0.f;
        #pragma unroll
        for (int e = 0; e < D_DIM / 32; e++) { float v = row[lane + 32 * e]; s += v * v; }
        #pragma unroll
        for (int o = 16; o > 0; o >>= 1) s += __shfl_xor_sync(0xffffffffu, s, o);
        if (lane == 0) g_cn[gw] = s;
    }
}

// ---------------- tile loaders ----------------------------------------------
__device__ __forceinline__ void load_a_tile(const float* __restrict__ A, int K,
                                            int m0, int k0, int ar, int aq, float v[8]) {
    const float* Ap = A + (size_t)(m0 + ar) * K + k0 + aq;
    if (k0 + 16 <= K) {
        float4 p0 = *(const float4*)Ap, p1 = *(const float4*)(Ap + 4);
        v[0]=p0.x; v[1]=p0.y; v[2]=p0.z; v[3]=p0.w; v[4]=p1.x; v[5]=p1.y; v[6]=p1.z; v[7]=p1.w;
    } else {
        #pragma unroll
        for (int j = 0; j < 8; j++) v[j] = (k0 + aq + j < K) ? Ap[j] : 0.f;
    }
}
__device__ __forceinline__ void load_b_tile(const float* __restrict__ B, int N, int K,
                                            int n0, int k0, int bk, int bq, float v[8]) {
    if (k0 + bk < K) {
        const float* Bp = B + (size_t)(k0 + bk) * N + n0 + bq;
        if (n0 + bq + 8 <= N) {
            float4 p0 = *(const float4*)Bp, p1 = *(const float4*)(Bp + 4);
            v[0]=p0.x; v[1]=p0.y; v[2]=p0.z; v[3]=p0.w; v[4]=p1.x; v[5]=p1.y; v[6]=p1.z; v[7]=p1.w;
        } else {
            #pragma unroll
            for (int j = 0; j < 8; j++) v[j] = (n0 + bq + j < N) ? Bp[j] : 0.f;
        }
    } else {
        #pragma unroll
        for (int j = 0; j < 8; j++) v[j] = 0.f;
    }
}

// ---------------- tensor-core GEMM: C = act(A @ B + bias) -------------------
// PR=true: 3-term split-tf32 (fp32-class accuracy). BM=BN=128, BK=16, 256 thr.
// 8 warps as 2x4; warp tile 64x32; mma m16n8k8 tf32.
template<bool PR, bool RELU>
__global__ __launch_bounds__(256)
void gemm_tc(const float* __restrict__ A, const float* __restrict__ B,
             const float* __restrict__ bias, float* __restrict__ C,
             int N, int K)
{
    __shared__ float Ah[128][20];
    __shared__ float Al[PR ? 128 : 1][PR ? 20 : 1];
    __shared__ float Bh[16][136];
    __shared__ float Bl[PR ? 16 : 1][PR ? 136 : 1];

    const int tid  = threadIdx.x;
    const int lane = tid & 31, warp = tid >> 5;
    const int g = lane >> 2, t = lane & 3;
    const int wm = warp >> 2, wn = warp & 3;
    const int m0 = blockIdx.y * 128, n0 = blockIdx.x * 128;

    const int ar = tid >> 1, aq = (tid & 1) * 8;
    const int bk = tid >> 4, bq = (tid & 15) * 8;

    float c[4][4][4] = {};
    float va[8], vb[8];
    load_a_tile(A, K, m0, 0, ar, aq, va);
    load_b_tile(B, N, K, n0, 0, bk, bq, vb);

    for (int k0 = 0; k0 < K; k0 += 16) {
        #pragma unroll
        for (int j = 0; j < 8; j++) {
            unsigned h = f2tf(va[j]);
            Ah[ar][aq + j] = __uint_as_float(h);
            if constexpr (PR) Al[ar][aq + j] = __uint_as_float(f2tf(va[j] - __uint_as_float(h)));
        }
        #pragma unroll
        for (int j = 0; j < 8; j++) {
            unsigned h = f2tf(vb[j]);
            Bh[bk][bq + j] = __uint_as_float(h);
            if constexpr (PR) Bl[bk][bq + j] = __uint_as_float(f2tf(vb[j] - __uint_as_float(h)));
        }
        __syncthreads();

        if (k0 + 16 < K) {
            load_a_tile(A, K, m0, k0 + 16, ar, aq, va);
            load_b_tile(B, N, K, n0, k0 + 16, bk, bq, vb);
        }

        #pragma unroll
        for (int kk = 0; kk < 16; kk += 8) {
            unsigned ah[4][4], bh[4][2];
            unsigned al[PR ? 4 : 1][4], bl[PR ? 4 : 1][2];
            #pragma unroll
            for (int i = 0; i < 4; i++) {
                int mb = wm * 64 + i * 16;
                ah[i][0] = __float_as_uint(Ah[mb + g    ][kk + t    ]);
                ah[i][1] = __float_as_uint(Ah[mb + g + 8][kk + t    ]);
                ah[i][2] = __float_as_uint(Ah[mb + g    ][kk + t + 4]);
                ah[i][3] = __float_as_uint(Ah[mb + g + 8][kk + t + 4]);
                if constexpr (PR) {
                    al[i][0] = __float_as_uint(Al[mb + g    ][kk + t    ]);
                    al[i][1] = __float_as_uint(Al[mb + g + 8][kk + t    ]);
                    al[i][2] = __float_as_uint(Al[mb + g    ][kk + t + 4]);
                    al[i][3] = __float_as_uint(Al[mb + g + 8][kk + t + 4]);
                }
            }
            #pragma unroll
            for (int j = 0; j < 4; j++) {
                int nb = wn * 32 + j * 8;
                bh[j][0] = __float_as_uint(Bh[kk + t    ][nb + g]);
                bh[j][1] = __float_as_uint(Bh[kk + t + 4][nb + g]);
                if constexpr (PR) {
                    bl[j][0] = __float_as_uint(Bl[kk + t    ][nb + g]);
                    bl[j][1] = __float_as_uint(Bl[kk + t + 4][nb + g]);
                }
            }
            #pragma unroll
            for (int i = 0; i < 4; i++)
                #pragma unroll
                for (int j = 0; j < 4; j++) {
                    mma_tf32(c[i][j], ah[i], bh[j]);
                    if constexpr (PR) {
                        mma_tf32(c[i][j], ah[i], bl[j]);
                        mma_tf32(c[i][j], al[i], bh[j]);
                    }
                }
        }
        __syncthreads();
    }

    #pragma unroll
    for (int j = 0; j < 4; j++) {
        int col0 = n0 + wn * 32 + j * 8 + t * 2;
        float b0 = (col0     < N) ? bias[col0]     : 0.f;
        float b1 = (col0 + 1 < N) ? bias[col0 + 1] : 0.f;
        #pragma unroll
        for (int i = 0; i < 4; i++) {
            int row0 = m0 + wm * 64 + i * 16 + g;
            float v00 = c[i][j][0] + b0, v01 = c[i][j][1] + b1;
            float v10 = c[i][j][2] + b0, v11 = c[i][j][3] + b1;
            if (RELU) {
                v00 = fmaxf(v00, 0.f); v01 = fmaxf(v01, 0.f);
                v10 = fmaxf(v10, 0.f); v11 = fmaxf(v11, 0.f);
            }
            if (col0 < N) {
                C[(size_t)row0 * N + col0]       = v00;
                C[(size_t)(row0 + 8) * N + col0] = v10;
            }
            if (col0 + 1 < N) {
                C[(size_t)row0 * N + col0 + 1]       = v01;
                C[(size_t)(row0 + 8) * N + col0 + 1] = v11;
            }
        }
    }
}

// ---------------- VQ: tf32 approx scores + exact fp32 algebraic rescore -----
__global__ __launch_bounds__(256)
void vq_tc(const float* __restrict__ R, const float* __restrict__ cb,
           int qoff, float* __restrict__ code_out)
{
    __shared__ float Ah[128][20];
    __shared__ float Bh[16][136];
    __shared__ float cns[K_CODES];
    __shared__ float rnrow[128];
    __shared__ unsigned rowminU[128];
    __shared__ unsigned long long rowbest[128];
    __shared__ int cand[VQ_CAP];
    __shared__ int ncand;
    __shared__ float red[256];

    const int tid  = threadIdx.x;
    const int lane = tid & 31, warp = tid >> 5;
    const int g = lane >> 2, t = lane & 3;
    const int wm = warp >> 2, wn = warp & 3;
    const int m0 = blockIdx.x * 128;

    const int ar = tid >> 1, aq = (tid & 1) * 8;
    const int nloc = tid >> 1, kq2 = (tid & 1) * 8;

    if (tid < 128) { rowminU[tid] = 0xFFFFFFFFu; rowbest[tid] = ~0ull; }
    if (tid == 0) ncand = 0;
    const float* cn = g_cn + qoff * K_CODES;
    #pragma unroll
    for (int i = tid; i < K_CODES; i += 256) cns[i] = cn[i];

    // per-row ||r||^2 (fp32), one warp per 16 rows
    for (int r = warp; r < 128; r += 8) {
        const float* rr = R + (size_t)(m0 + r) * D_DIM;
        float s = 0.f;
        #pragma unroll
        for (int e = 0; e < 8; e++) { float v = rr[lane + 32 * e]; s = fmaf(v, v, s); }
        #pragma unroll
        for (int o = 16; o > 0; o >>= 1) s += __shfl_xor_sync(0xffffffffu, s, o);
        if (lane == 0) rnrow[r] = s;
    }
    __syncthreads();

    for (int c0 = 0; c0 < K_CODES; c0 += 128) {
        float c[4][4][4] = {};
        float va[8], vbv[8];
        load_a_tile(R, D_DIM, m0, 0, ar, aq, va);
        {
            const float* Cp = cb + (size_t)(c0 + nloc) * D_DIM + kq2;
            float4 p0 = *(const float4*)Cp, p1 = *(const float4*)(Cp + 4);
            vbv[0]=p0.x; vbv[1]=p0.y; vbv[2]=p0.z; vbv[3]=p0.w;
            vbv[4]=p1.x; vbv[5]=p1.y; vbv[6]=p1.z; vbv[7]=p1.w;
        }

        for (int k0 = 0; k0 < D_DIM; k0 += 16) {
            #pragma unroll
            for (int j = 0; j < 8; j++) Ah[ar][aq + j] = __uint_as_float(f2tf(va[j]));
            #pragma unroll
            for (int j = 0; j < 8; j++) Bh[kq2 + j][nloc] = __uint_as_float(f2tf(vbv[j]));
            __syncthreads();

            if (k0 + 16 < D_DIM) {
                load_a_tile(R, D_DIM, m0, k0 + 16, ar, aq, va);
                const float* Cp = cb + (size_t)(c0 + nloc) * D_DIM + k0 + 16 + kq2;
                float4 p0 = *(const float4*)Cp, p1 = *(const float4*)(Cp + 4);
                vbv[0]=p0.x; vbv[1]=p0.y; vbv[2]=p0.z; vbv[3]=p0.w;
                vbv[4]=p1.x; vbv[5]=p1.y; vbv[6]=p1.z; vbv[7]=p1.w;
            }

            #pragma unroll
            for (int kk = 0; kk < 16; kk += 8) {
                unsigned ah[4][4], bh[4][2];
                #pragma unroll
                for (int i = 0; i < 4; i++) {
                    int mb = wm * 64 + i * 16;
                    ah[i][0] = __float_as_uint(Ah[mb + g    ][kk + t    ]);
                    ah[i][1] = __float_as_uint(Ah[mb + g + 8][kk + t    ]);
                    ah[i][2] = __float_as_uint(Ah[mb + g    ][kk + t + 4]);
                    ah[i][3] = __float_as_uint(Ah[mb + g + 8][kk + t + 4]);
                }
                #pragma unroll
                for (int j = 0; j < 4; j++) {
                    int nb = wn * 32 + j * 8;
                    bh[j][0] = __float_as_uint(Bh[kk + t    ][nb + g]);
                    bh[j][1] = __float_as_uint(Bh[kk + t + 4][nb + g]);
                }
                #pragma unroll
                for (int i = 0; i < 4; i++)
                    #pragma unroll
                    for (int j = 0; j < 4; j++) mma_tf32(c[i][j], ah[i], bh[j]);
            }
            __syncthreads();
        }

        // approx scores -> running row minima
        float smin[8];
        #pragma unroll
        for (int s = 0; s < 8; s++) smin[s] = FLT_MAX;
        #pragma unroll
        for (int i = 0; i < 4; i++)
            #pragma unroll
            for (int j = 0; j < 4; j++) {
                int cA = c0 + wn * 32 + j * 8 + t * 2;
                float cn0 = cns[cA], cn1 = cns[cA + 1];
                float s00 = fmaf(-2.f, c[i][j][0], cn0);
                float s01 = fmaf(-2.f, c[i][j][1], cn1);
                float s10 = fmaf(-2.f, c[i][j][2], cn0);
                float s11 = fmaf(-2.f, c[i][j][3], cn1);
                smin[2*i]   = fminf(smin[2*i],   fminf(s00, s01));
                smin[2*i+1] = fminf(smin[2*i+1], fminf(s10, s11));
            }
        #pragma unroll
        for (int i = 0; i < 4; i++) {
            int r0 = wm * 64 + i * 16 + g;
            atomicMin(&rowminU[r0],     ordf(smin[2*i]));
            atomicMin(&rowminU[r0 + 8], ordf(smin[2*i+1]));
        }
        __syncthreads();

        // candidate collection (running min >= final min => complete superset)
        #pragma unroll
        for (int i = 0; i < 4; i++) {
            int r0 = wm * 64 + i * 16 + g;
            float th0 = iordf(rowminU[r0])     + VQ_MARGIN;
            float th1 = iordf(rowminU[r0 + 8]) + VQ_MARGIN;
            #pragma unroll
            for (int j = 0; j < 4; j++) {
                int cA = c0 + wn * 32 + j * 8 + t * 2;
                float cn0 = cns[cA], cn1 = cns[cA + 1];
                float s00 = fmaf(-2.f, c[i][j][0], cn0);
                float s01 = fmaf(-2.f, c[i][j][1], cn1);
                float s10 = fmaf(-2.f, c[i][j][2], cn0);
                float s11 = fmaf(-2.f, c[i][j][3], cn1);
                if (s00 <= th0) { int p = atomicAdd(&ncand, 1); if (p < VQ_CAP) cand[p] = (r0 << 10) | cA; }
                if (s01 <= th0) { int p = atomicAdd(&ncand, 1); if (p < VQ_CAP) cand[p] = (r0 << 10) | (cA + 1); }
                if (s10 <= th1) { int p = atomicAdd(&ncand, 1); if (p < VQ_CAP) cand[p] = ((r0 + 8) << 10) | cA; }
                if (s11 <= th1) { int p = atomicAdd(&ncand, 1); if (p < VQ_CAP) cand[p] = ((r0 + 8) << 10) | (cA + 1); }
            }
        }
        __syncthreads();
    }

    // exact fp32 rescore, algebraic form (matches reference): s = ||c||^2 - 2 r.c
    int nc = min(ncand, VQ_CAP);
    for (int ci = warp; ci < nc; ci += 8) {
        int pk = cand[ci];
        int lr = pk >> 10, code = pk & 1023;
        const float* rr = R  + (size_t)(m0 + lr) * D_DIM;
        const float* cc = cb + (size_t)code * D_DIM;
        float acc = 0.f;
        #pragma unroll
        for (int e = 0; e < 8; e++) acc = fmaf(rr[lane + e * 32], cc[lane + e * 32], acc);
        #pragma unroll
        for (int o = 16; o > 0; o >>= 1) acc += __shfl_xor_sync(0xffffffffu, acc, o);
        if (lane == 0) {
            float s = fmaf(-2.f, acc, cns[code]);
            atomicMin(&rowbest[lr],
                      ((unsigned long long)ordf(s) << 32) | (unsigned)code);
        }
    }
    __syncthreads();

    float dist = 0.f;
    if (tid < 128) {
        unsigned long long b = rowbest[tid];
        int code = (int)(b & 0xFFFFFFFFu);
        dist = iordf((unsigned)(b >> 32)) + rnrow[tid];
        int n = m0 + tid;
        g_idx[n * NQ + qoff] = code;
        code_out[(size_t)n * NQ] = (float)code;
    }
    red[tid] = dist;
    __syncthreads();
    for (int s = 128; s > 0; s >>= 1) {
        if (tid < s) red[tid] += red[tid + s];
        __syncthreads();
    }
    if (tid == 0) atomicAdd(&g_vq_sum, (double)red[0]);
}

// ---------------- gathers ----------------------------------------------------
__global__ void gather_residual(const float* __restrict__ z, const float* __restrict__ cb0) {
    int n = blockIdx.x, e = threadIdx.x;
    int c = g_idx[n * NQ + 0];
    float zv = z[(size_t)n * D_DIM + e];
    float cv = cb0[(size_t)c * D_DIM + e];
    g_r[(size_t)n * D_DIM + e] = zv - cv;
    g_q[(size_t)n * D_DIM + e] = cv;
}
__global__ void gather_add(const float* __restrict__ cb1) {
    int n = blockIdx.x, e = threadIdx.x;
    int c = g_idx[n * NQ + 1];
    g_q[(size_t)n * D_DIM + e] += cb1[(size_t)c * D_DIM + e];
}

// ---------------- L1 reduction -----------------------------------------------
__global__ void l1_kernel(const float* __restrict__ x) {
    const size_t TOT = (size_t)NROWS * IN_DIM;
    float s = 0.f;
    for (size_t i = (size_t)blockIdx.x * blockDim.x + threadIdx.x; i < TOT;
         i += (size_t)gridDim.x * blockDim.x)
        s += fabsf(x[i] - g_dec[i]);
    __shared__ float red[256];
    red[threadIdx.x] = s;
    __syncthreads();
    for (int o = 128; o > 0; o >>= 1) {
        if (threadIdx.x < o) red[threadIdx.x] += red[threadIdx.x + o];
        __syncthreads();
    }
    if (threadIdx.x == 0) atomicAdd(&g_enc_sum, (double)red[0]);
}

// ---------------- finalize ---------------------------------------------------
__global__ void finalize_kernel(float* out, int write_loss) {
    if (write_loss) {
        double enc = g_enc_sum / ((double)NROWS * IN_DIM);
        double vq  = g_vq_sum  / ((double)NROWS * D_DIM);
        out[0] = (float)(enc + 5.0 * vq);
    }
}

// ---------------- launch -----------------------------------------------------
extern "C" void kernel_launch(void* const* d_in, const int* in_sizes, int n_in,
                              void* d_out, int out_size)
{
    const float* state = (const float*)d_in[0];
    const float* ew1 = (const float*)d_in[1];  const float* eb1 = (const float*)d_in[2];
    const float* ew2 = (const float*)d_in[3];  const float* eb2 = (const float*)d_in[4];
    const float* ew3 = (const float*)d_in[5];  const float* eb3 = (const float*)d_in[6];
    const float* dw1 = (const float*)d_in[7];  const float* db1 = (const float*)d_in[8];
    const float* dw2 = (const float*)d_in[9];  const float* db2 = (const float*)d_in[10];
    const float* dw3 = (const float*)d_in[11]; const float* db3 = (const float*)d_in[12];
    const float* cbs = (const float*)d_in[13];

    float* out = (float*)d_out;
    int code_base = out_size - NROWS * NQ;
    if (code_base < 0) code_base = 0;
    float* codes = out + code_base;

    float *p_h1, *p_h2, *p_z, *p_r, *p_q, *p_dec;
    cudaGetSymbolAddress((void**)&p_h1,  g_h1);
    cudaGetSymbolAddress((void**)&p_h2,  g_h2);
    cudaGetSymbolAddress((void**)&p_z,   g_z);
    cudaGetSymbolAddress((void**)&p_r,   g_r);
    cudaGetSymbolAddress((void**)&p_q,   g_q);
    cudaGetSymbolAddress((void**)&p_dec, g_dec);

    const int MB = NROWS / 128;

    zero_acc_kernel<<<1, 1>>>();
    cnorm_kernel<<<(NQ * K_CODES * 32) / 256, 256>>>(cbs);

    // encoder: 3-term split-tf32 (fp32-class accuracy protects argmin)
    gemm_tc<true, true ><<<dim3(H_DIM / 128, MB), 256>>>(state, ew1, eb1, p_h1, H_DIM, IN_DIM);
    gemm_tc<true, true ><<<dim3(H_DIM / 128, MB), 256>>>(p_h1,  ew2, eb2, p_h2, H_DIM, H_DIM);
    gemm_tc<true, false><<<dim3(D_DIM / 128, MB), 256>>>(p_h2,  ew3, eb3, p_z,  D_DIM, H_DIM);

    // residual VQ: approx tf32 scores + exact fp32 rescore
    vq_tc<<<MB, 256>>>(p_z, cbs, 0, codes + 0);
    gather_residual<<<NROWS, D_DIM>>>(p_z, cbs);
    vq_tc<<<MB, 256>>>(p_r, cbs + (size_t)K_CODES * D_DIM, 1, codes + 1);
    gather_add<<<NROWS, D_DIM>>>(cbs + (size_t)K_CODES * D_DIM);

    // decoder: plain tf32 (L1-mean averages out tf32 noise)
    gemm_tc<false, true ><<<dim3(H_DIM / 128, MB), 256>>>(p_q,  dw1, db1, p_h1, H_DIM, D_DIM);
    gemm_tc<false, true ><<<dim3(H_DIM / 128, MB), 256>>>(p_h1, dw2, db2, p_h2, H_DIM, H_DIM);
    gemm_tc<false, false><<<dim3(1, MB),           256>>>(p_h2, dw3, db3, p_dec, IN_DIM, H_DIM);
    l1_kernel<<<1024, 256>>>(state);

    finalize_kernel<<<1, 1>>>(out, code_base >= 1);
}

// round 14
// speedup vs baseline: 1.9015x; 1.0744x over previous
#include <cuda_runtime.h>
#include <math.h>
#include <float.h>

#define NROWS   131072
#define IN_DIM  56
#define H_DIM   512
#define D_DIM   256
#define K_CODES 1024
#define NQ      2
#define VQ_CAP  4096
#define VQ_MARGIN 2.0f

// ---------------- scratch (static device globals; no allocations) ----------
__device__ float g_h1[(size_t)NROWS * H_DIM];
__device__ float g_h2[(size_t)NROWS * H_DIM];
__device__ float g_z [(size_t)NROWS * D_DIM];
__device__ float g_r [(size_t)NROWS * D_DIM];
__device__ float g_q [(size_t)NROWS * D_DIM];
__device__ float g_dec[(size_t)NROWS * IN_DIM];
__device__ int    g_idx[NROWS * NQ];
__device__ float  g_cn[NQ * K_CODES];
__device__ double g_vq_sum;
__device__ double g_enc_sum;

// ---------------- helpers ----------------------------------------------------
__device__ __forceinline__ unsigned f2tf(float x) {
    unsigned u; asm("cvt.rna.tf32.f32 %0, %1;" : "=r"(u) : "f"(x)); return u;
}
__device__ __forceinline__ void mma_tf32(float c[4], const unsigned a[4], const unsigned b[2]) {
    asm volatile("mma.sync.aligned.m16n8k8.row.col.f32.tf32.tf32.f32 "
        "{%0,%1,%2,%3}, {%4,%5,%6,%7}, {%8,%9}, {%0,%1,%2,%3};"
        : "+f"(c[0]), "+f"(c[1]), "+f"(c[2]), "+f"(c[3])
        : "r"(a[0]), "r"(a[1]), "r"(a[2]), "r"(a[3]), "r"(b[0]), "r"(b[1]));
}
// order-preserving float<->uint maps (monotone, handles negatives)
__device__ __forceinline__ unsigned ordf(float f) {
    unsigned u = __float_as_uint(f);
    return (u >> 31) ? ~u : (u | 0x80000000u);
}
__device__ __forceinline__ float iordf(unsigned u) {
    return __uint_as_float((u >> 31) ? (u & 0x7FFFFFFFu) : ~u);
}

// ---------------- misc small kernels ---------------------------------------
__global__ void zero_acc_kernel() { g_vq_sum = 0.0; g_enc_sum = 0.0; }

__global__ void cnorm_kernel(const float* __restrict__ cbs) {
    int gw   = (blockIdx.x * blockDim.x + threadIdx.x) >> 5;
    int lane = threadIdx.x & 31;
    if (gw < NQ * K_CODES) {
        const float* row = cbs + (size_t)gw * D_DIM;
        float s = 0.f;
        #pragma unroll
        for (int e = 0; e < D_DIM / 32; e++) { float v = row[lane + 32 * e]; s += v * v; }
        #pragma unroll
        for (int o = 16; o > 0; o >>= 1) s += __shfl_xor_sync(0xffffffffu, s, o);
        if (lane == 0) g_cn[gw] = s;
    }
}

// ---------------- tile loaders ----------------------------------------------
__device__ __forceinline__ void load_a_tile(const float* __restrict__ A, int K,
                                            int m0, int k0, int ar, int aq, float v[8]) {
    const float* Ap = A + (size_t)(m0 + ar) * K + k0 + aq;
    if (k0 + 16 <= K) {
        float4 p0 = *(const float4*)Ap, p1 = *(const float4*)(Ap + 4);
        v[0]=p0.x; v[1]=p0.y; v[2]=p0.z; v[3]=p0.w; v[4]=p1.x; v[5]=p1.y; v[6]=p1.z; v[7]=p1.w;
    } else {
        #pragma unroll
        for (int j = 0; j < 8; j++) v[j] = (k0 + aq + j < K) ? Ap[j] : 0.f;
    }
}
__device__ __forceinline__ void load_b_tile(const float* __restrict__ B, int N, int K,
                                            int n0, int k0, int bk, int bq, float v[8]) {
    if (k0 + bk < K) {
        const float* Bp = B + (size_t)(k0 + bk) * N + n0 + bq;
        if (n0 + bq + 8 <= N) {
            float4 p0 = *(const float4*)Bp, p1 = *(const float4*)(Bp + 4);
            v[0]=p0.x; v[1]=p0.y; v[2]=p0.z; v[3]=p0.w; v[4]=p1.x; v[5]=p1.y; v[6]=p1.z; v[7]=p1.w;
        } else {
            #pragma unroll
            for (int j = 0; j < 8; j++) v[j] = (n0 + bq + j < N) ? Bp[j] : 0.f;
        }
    } else {
        #pragma unroll
        for (int j = 0; j < 8; j++) v[j] = 0.f;
    }
}

// ---------------- tensor-core GEMM: C = act(A @ B + bias) -------------------
// PR=true: 3-term split-tf32 (fp32-class accuracy). BM=BN=128, BK=16, 256 thr.
// 8 warps as 2x4; warp tile 64x32; mma m16n8k8 tf32. 2 CTAs/SM target.
template<bool PR, bool RELU>
__global__ __launch_bounds__(256, 2)
void gemm_tc(const float* __restrict__ A, const float* __restrict__ B,
             const float* __restrict__ bias, float* __restrict__ C,
             int N, int K)
{
    __shared__ float Ah[128][20];
    __shared__ float Al[PR ? 128 : 1][PR ? 20 : 1];
    __shared__ float Bh[16][136];
    __shared__ float Bl[PR ? 16 : 1][PR ? 136 : 1];

    const int tid  = threadIdx.x;
    const int lane = tid & 31, warp = tid >> 5;
    const int g = lane >> 2, t = lane & 3;
    const int wm = warp >> 2, wn = warp & 3;
    const int m0 = blockIdx.y * 128, n0 = blockIdx.x * 128;

    const int ar = tid >> 1, aq = (tid & 1) * 8;
    const int bk = tid >> 4, bq = (tid & 15) * 8;

    float c[4][4][4] = {};
    float va[8], vb[8];
    load_a_tile(A, K, m0, 0, ar, aq, va);
    load_b_tile(B, N, K, n0, 0, bk, bq, vb);

    for (int k0 = 0; k0 < K; k0 += 16) {
        #pragma unroll
        for (int j = 0; j < 8; j++) {
            unsigned h = f2tf(va[j]);
            Ah[ar][aq + j] = __uint_as_float(h);
            if constexpr (PR) Al[ar][aq + j] = __uint_as_float(f2tf(va[j] - __uint_as_float(h)));
        }
        #pragma unroll
        for (int j = 0; j < 8; j++) {
            unsigned h = f2tf(vb[j]);
            Bh[bk][bq + j] = __uint_as_float(h);
            if constexpr (PR) Bl[bk][bq + j] = __uint_as_float(f2tf(vb[j] - __uint_as_float(h)));
        }
        __syncthreads();

        if (k0 + 16 < K) {
            load_a_tile(A, K, m0, k0 + 16, ar, aq, va);
            load_b_tile(B, N, K, n0, k0 + 16, bk, bq, vb);
        }

        #pragma unroll
        for (int kk = 0; kk < 16; kk += 8) {
            // hold B fragments for the whole kk-step (16 regs + 16 when PR)
            unsigned bh[4][2], bl[PR ? 4 : 1][2];
            #pragma unroll
            for (int j = 0; j < 4; j++) {
                int nb = wn * 32 + j * 8;
                bh[j][0] = __float_as_uint(Bh[kk + t    ][nb + g]);
                bh[j][1] = __float_as_uint(Bh[kk + t + 4][nb + g]);
                if constexpr (PR) {
                    bl[j][0] = __float_as_uint(Bl[kk + t    ][nb + g]);
                    bl[j][1] = __float_as_uint(Bl[kk + t + 4][nb + g]);
                }
            }
            // A fragments per-i: shrinks live registers (occupancy), math order
            // per accumulator unchanged (kk -> hh, hl, lh) => bit-identical.
            #pragma unroll
            for (int i = 0; i < 4; i++) {
                int mb = wm * 64 + i * 16;
                unsigned ah[4], al[PR ? 4 : 1];
                ah[0] = __float_as_uint(Ah[mb + g    ][kk + t    ]);
                ah[1] = __float_as_uint(Ah[mb + g + 8][kk + t    ]);
                ah[2] = __float_as_uint(Ah[mb + g    ][kk + t + 4]);
                ah[3] = __float_as_uint(Ah[mb + g + 8][kk + t + 4]);
                if constexpr (PR) {
                    al[0] = __float_as_uint(Al[mb + g    ][kk + t    ]);
                    al[1] = __float_as_uint(Al[mb + g + 8][kk + t    ]);
                    al[2] = __float_as_uint(Al[mb + g    ][kk + t + 4]);
                    al[3] = __float_as_uint(Al[mb + g + 8][kk + t + 4]);
                }
                #pragma unroll
                for (int j = 0; j < 4; j++) {
                    mma_tf32(c[i][j], ah, bh[j]);
                    if constexpr (PR) {
                        mma_tf32(c[i][j], ah, bl[j]);
                        mma_tf32(c[i][j], al, bh[j]);
                    }
                }
            }
        }
        __syncthreads();
    }

    #pragma unroll
    for (int j = 0; j < 4; j++) {
        int col0 = n0 + wn * 32 + j * 8 + t * 2;
        float b0 = (col0     < N) ? bias[col0]     : 0.f;
        float b1 = (col0 + 1 < N) ? bias[col0 + 1] : 0.f;
        #pragma unroll
        for (int i = 0; i < 4; i++) {
            int row0 = m0 + wm * 64 + i * 16 + g;
            float v00 = c[i][j][0] + b0, v01 = c[i][j][1] + b1;
            float v10 = c[i][j][2] + b0, v11 = c[i][j][3] + b1;
            if (RELU) {
                v00 = fmaxf(v00, 0.f); v01 = fmaxf(v01, 0.f);
                v10 = fmaxf(v10, 0.f); v11 = fmaxf(v11, 0.f);
            }
            if (col0 < N) {
                C[(size_t)row0 * N + col0]       = v00;
                C[(size_t)(row0 + 8) * N + col0] = v10;
            }
            if (col0 + 1 < N) {
                C[(size_t)row0 * N + col0 + 1]       = v01;
                C[(size_t)(row0 + 8) * N + col0 + 1] = v11;
            }
        }
    }
}

// ---------------- VQ: tf32 approx scores + exact fp32 algebraic rescore -----
__global__ __launch_bounds__(256, 2)
void vq_tc(const float* __restrict__ R, const float* __restrict__ cb,
           int qoff, float* __restrict__ code_out)
{
    __shared__ float Ah[128][20];
    __shared__ float Bh[16][136];
    __shared__ float cns[K_CODES];
    __shared__ float rnrow[128];
    __shared__ unsigned rowminU[128];
    __shared__ unsigned long long rowbest[128];
    __shared__ int cand[VQ_CAP];
    __shared__ int ncand;
    __shared__ float red[256];

    const int tid  = threadIdx.x;
    const int lane = tid & 31, warp = tid >> 5;
    const int g = lane >> 2, t = lane & 3;
    const int wm = warp >> 2, wn = warp & 3;
    const int m0 = blockIdx.x * 128;

    const int ar = tid >> 1, aq = (tid & 1) * 8;
    const int nloc = tid >> 1, kq2 = (tid & 1) * 8;

    if (tid < 128) { rowminU[tid] = 0xFFFFFFFFu; rowbest[tid] = ~0ull; }
    if (tid == 0) ncand = 0;
    const float* cn = g_cn + qoff * K_CODES;
    #pragma unroll
    for (int i = tid; i < K_CODES; i += 256) cns[i] = cn[i];

    // per-row ||r||^2 (fp32), one warp per 16 rows
    for (int r = warp; r < 128; r += 8) {
        const float* rr = R + (size_t)(m0 + r) * D_DIM;
        float s = 0.f;
        #pragma unroll
        for (int e = 0; e < 8; e++) { float v = rr[lane + 32 * e]; s = fmaf(v, v, s); }
        #pragma unroll
        for (int o = 16; o > 0; o >>= 1) s += __shfl_xor_sync(0xffffffffu, s, o);
        if (lane == 0) rnrow[r] = s;
    }
    __syncthreads();

    for (int c0 = 0; c0 < K_CODES; c0 += 128) {
        float c[4][4][4] = {};
        float va[8], vbv[8];
        load_a_tile(R, D_DIM, m0, 0, ar, aq, va);
        {
            const float* Cp = cb + (size_t)(c0 + nloc) * D_DIM + kq2;
            float4 p0 = *(const float4*)Cp, p1 = *(const float4*)(Cp + 4);
            vbv[0]=p0.x; vbv[1]=p0.y; vbv[2]=p0.z; vbv[3]=p0.w;
            vbv[4]=p1.x; vbv[5]=p1.y; vbv[6]=p1.z; vbv[7]=p1.w;
        }

        for (int k0 = 0; k0 < D_DIM; k0 += 16) {
            #pragma unroll
            for (int j = 0; j < 8; j++) Ah[ar][aq + j] = __uint_as_float(f2tf(va[j]));
            #pragma unroll
            for (int j = 0; j < 8; j++) Bh[kq2 + j][nloc] = __uint_as_float(f2tf(vbv[j]));
            __syncthreads();

            if (k0 + 16 < D_DIM) {
                load_a_tile(R, D_DIM, m0, k0 + 16, ar, aq, va);
                const float* Cp = cb + (size_t)(c0 + nloc) * D_DIM + k0 + 16 + kq2;
                float4 p0 = *(const float4*)Cp, p1 = *(const float4*)(Cp + 4);
                vbv[0]=p0.x; vbv[1]=p0.y; vbv[2]=p0.z; vbv[3]=p0.w;
                vbv[4]=p1.x; vbv[5]=p1.y; vbv[6]=p1.z; vbv[7]=p1.w;
            }

            #pragma unroll
            for (int kk = 0; kk < 16; kk += 8) {
                unsigned bh[4][2];
                #pragma unroll
                for (int j = 0; j < 4; j++) {
                    int nb = wn * 32 + j * 8;
                    bh[j][0] = __float_as_uint(Bh[kk + t    ][nb + g]);
                    bh[j][1] = __float_as_uint(Bh[kk + t + 4][nb + g]);
                }
                #pragma unroll
                for (int i = 0; i < 4; i++) {
                    int mb = wm * 64 + i * 16;
                    unsigned ah[4];
                    ah[0] = __float_as_uint(Ah[mb + g    ][kk + t    ]);
                    ah[1] = __float_as_uint(Ah[mb + g + 8][kk + t    ]);
                    ah[2] = __float_as_uint(Ah[mb + g    ][kk + t + 4]);
                    ah[3] = __float_as_uint(Ah[mb + g + 8][kk + t + 4]);
                    #pragma unroll
                    for (int j = 0; j < 4; j++) mma_tf32(c[i][j], ah, bh[j]);
                }
            }
            __syncthreads();
        }

        // approx scores -> running row minima
        float smin[8];
        #pragma unroll
        for (int s = 0; s < 8; s++) smin[s] = FLT_MAX;
        #pragma unroll
        for (int i = 0; i < 4; i++)
            #pragma unroll
            for (int j = 0; j < 4; j++) {
                int cA = c0 + wn * 32 + j * 8 + t * 2;
                float cn0 = cns[cA], cn1 = cns[cA + 1];
                float s00 = fmaf(-2.f, c[i][j][0], cn0);
                float s01 = fmaf(-2.f, c[i][j][1], cn1);
                float s10 = fmaf(-2.f, c[i][j][2], cn0);
                float s11 = fmaf(-2.f, c[i][j][3], cn1);
                smin[2*i]   = fminf(smin[2*i],   fminf(s00, s01));
                smin[2*i+1] = fminf(smin[2*i+1], fminf(s10, s11));
            }
        #pragma unroll
        for (int i = 0; i < 4; i++) {
            int r0 = wm * 64 + i * 16 + g;
            atomicMin(&rowminU[r0],     ordf(smin[2*i]));
            atomicMin(&rowminU[r0 + 8], ordf(smin[2*i+1]));
        }
        __syncthreads();

        // candidate collection (running min >= final min => complete superset)
        #pragma unroll
        for (int i = 0; i < 4; i++) {
            int r0 = wm * 64 + i * 16 + g;
            float th0 = iordf(rowminU[r0])     + VQ_MARGIN;
            float th1 = iordf(rowminU[r0 + 8]) + VQ_MARGIN;
            #pragma unroll
            for (int j = 0; j < 4; j++) {
                int cA = c0 + wn * 32 + j * 8 + t * 2;
                float cn0 = cns[cA], cn1 = cns[cA + 1];
                float s00 = fmaf(-2.f, c[i][j][0], cn0);
                float s01 = fmaf(-2.f, c[i][j][1], cn1);
                float s10 = fmaf(-2.f, c[i][j][2], cn0);
                float s11 = fmaf(-2.f, c[i][j][3], cn1);
                if (s00 <= th0) { int p = atomicAdd(&ncand, 1); if (p < VQ_CAP) cand[p] = (r0 << 10) | cA; }
                if (s01 <= th0) { int p = atomicAdd(&ncand, 1); if (p < VQ_CAP) cand[p] = (r0 << 10) | (cA + 1); }
                if (s10 <= th1) { int p = atomicAdd(&ncand, 1); if (p < VQ_CAP) cand[p] = ((r0 + 8) << 10) | cA; }
                if (s11 <= th1) { int p = atomicAdd(&ncand, 1); if (p < VQ_CAP) cand[p] = ((r0 + 8) << 10) | (cA + 1); }
            }
        }
        __syncthreads();
    }

    // exact fp32 rescore, algebraic form (matches reference): s = ||c||^2 - 2 r.c
    int nc = min(ncand, VQ_CAP);
    for (int ci = warp; ci < nc; ci += 8) {
        int pk = cand[ci];
        int lr = pk >> 10, code = pk & 1023;
        const float* rr = R  + (size_t)(m0 + lr) * D_DIM;
        const float* cc = cb + (size_t)code * D_DIM;
        float acc = 0.f;
        #pragma unroll
        for (int e = 0; e < 8; e++) acc = fmaf(rr[lane + e * 32], cc[lane + e * 32], acc);
        #pragma unroll
        for (int o = 16; o > 0; o >>= 1) acc += __shfl_xor_sync(0xffffffffu, acc, o);
        if (lane == 0) {
            float s = fmaf(-2.f, acc, cns[code]);
            atomicMin(&rowbest[lr],
                      ((unsigned long long)ordf(s) << 32) | (unsigned)code);
        }
    }
    __syncthreads();

    float dist = 0.f;
    if (tid < 128) {
        unsigned long long b = rowbest[tid];
        int code = (int)(b & 0xFFFFFFFFu);
        dist = iordf((unsigned)(b >> 32)) + rnrow[tid];
        int n = m0 + tid;
        g_idx[n * NQ + qoff] = code;
        code_out[(size_t)n * NQ] = (float)code;
    }
    red[tid] = dist;
    __syncthreads();
    for (int s = 128; s > 0; s >>= 1) {
        if (tid < s) red[tid] += red[tid + s];
        __syncthreads();
    }
    if (tid == 0) atomicAdd(&g_vq_sum, (double)red[0]);
}

// ---------------- gathers ----------------------------------------------------
__global__ void gather_residual(const float* __restrict__ z, const float* __restrict__ cb0) {
    int n = blockIdx.x, e = threadIdx.x;
    int c = g_idx[n * NQ + 0];
    float zv = z[(size_t)n * D_DIM + e];
    float cv = cb0[(size_t)c * D_DIM + e];
    g_r[(size_t)n * D_DIM + e] = zv - cv;
    g_q[(size_t)n * D_DIM + e] = cv;
}
__global__ void gather_add(const float* __restrict__ cb1) {
    int n = blockIdx.x, e = threadIdx.x;
    int c = g_idx[n * NQ + 1];
    g_q[(size_t)n * D_DIM + e] += cb1[(size_t)c * D_DIM + e];
}

// ---------------- L1 reduction -----------------------------------------------
__global__ void l1_kernel(const float* __restrict__ x) {
    const size_t TOT = (size_t)NROWS * IN_DIM;
    float s = 0.f;
    for (size_t i = (size_t)blockIdx.x * blockDim.x + threadIdx.x; i < TOT;
         i += (size_t)gridDim.x * blockDim.x)
        s += fabsf(x[i] - g_dec[i]);
    __shared__ float red[256];
    red[threadIdx.x] = s;
    __syncthreads();
    for (int o = 128; o > 0; o >>= 1) {
        if (threadIdx.x < o) red[threadIdx.x] += red[threadIdx.x + o];
        __syncthreads();
    }
    if (threadIdx.x == 0) atomicAdd(&g_enc_sum, (double)red[0]);
}

// ---------------- finalize ---------------------------------------------------
__global__ void finalize_kernel(float* out, int write_loss) {
    if (write_loss) {
        double enc = g_enc_sum / ((double)NROWS * IN_DIM);
        double vq  = g_vq_sum  / ((double)NROWS * D_DIM);
        out[0] = (float)(enc + 5.0 * vq);
    }
}

// ---------------- launch -----------------------------------------------------
extern "C" void kernel_launch(void* const* d_in, const int* in_sizes, int n_in,
                              void* d_out, int out_size)
{
    const float* state = (const float*)d_in[0];
    const float* ew1 = (const float*)d_in[1];  const float* eb1 = (const float*)d_in[2];
    const float* ew2 = (const float*)d_in[3];  const float* eb2 = (const float*)d_in[4];
    const float* ew3 = (const float*)d_in[5];  const float* eb3 = (const float*)d_in[6];
    const float* dw1 = (const float*)d_in[7];  const float* db1 = (const float*)d_in[8];
    const float* dw2 = (const float*)d_in[9];  const float* db2 = (const float*)d_in[10];
    const float* dw3 = (const float*)d_in[11]; const float* db3 = (const float*)d_in[12];
    const float* cbs = (const float*)d_in[13];

    float* out = (float*)d_out;
    int code_base = out_size - NROWS * NQ;
    if (code_base < 0) code_base = 0;
    float* codes = out + code_base;

    float *p_h1, *p_h2, *p_z, *p_r, *p_q, *p_dec;
    cudaGetSymbolAddress((void**)&p_h1,  g_h1);
    cudaGetSymbolAddress((void**)&p_h2,  g_h2);
    cudaGetSymbolAddress((void**)&p_z,   g_z);
    cudaGetSymbolAddress((void**)&p_r,   g_r);
    cudaGetSymbolAddress((void**)&p_q,   g_q);
    cudaGetSymbolAddress((void**)&p_dec, g_dec);

    const int MB = NROWS / 128;

    zero_acc_kernel<<<1, 1>>>();
    cnorm_kernel<<<(NQ * K_CODES * 32) / 256, 256>>>(cbs);

    // encoder: 3-term split-tf32 (fp32-class accuracy protects argmin)
    gemm_tc<true, true ><<<dim3(H_DIM / 128, MB), 256>>>(state, ew1, eb1, p_h1, H_DIM, IN_DIM);
    gemm_tc<true, true ><<<dim3(H_DIM / 128, MB), 256>>>(p_h1,  ew2, eb2, p_h2, H_DIM, H_DIM);
    gemm_tc<true, false><<<dim3(D_DIM / 128, MB), 256>>>(p_h2,  ew3, eb3, p_z,  D_DIM, H_DIM);

    // residual VQ: approx tf32 scores + exact fp32 rescore
    vq_tc<<<MB, 256>>>(p_z, cbs, 0, codes + 0);
    gather_residual<<<NROWS, D_DIM>>>(p_z, cbs);
    vq_tc<<<MB, 256>>>(p_r, cbs + (size_t)K_CODES * D_DIM, 1, codes + 1);
    gather_add<<<NROWS, D_DIM>>>(cbs + (size_t)K_CODES * D_DIM);

    // decoder: plain tf32 (L1-mean averages out tf32 noise)
    gemm_tc<false, true ><<<dim3(H_DIM / 128, MB), 256>>>(p_q,  dw1, db1, p_h1, H_DIM, D_DIM);
    gemm_tc<false, true ><<<dim3(H_DIM / 128, MB), 256>>>(p_h1, dw2, db2, p_h2, H_DIM, H_DIM);
    gemm_tc<false, false><<<dim3(1, MB),           256>>>(p_h2, dw3, db3, p_dec, IN_DIM, H_DIM);
    l1_kernel<<<1024, 256>>>(state);

    finalize_kernel<<<1, 1>>>(out, code_base >= 1);
}

// round 16
// speedup vs baseline: 2.1212x; 1.1155x over previous
#include <cuda_runtime.h>
#include <math.h>
#include <float.h>

#define NROWS   131072
#define IN_DIM  56
#define H_DIM   512
#define D_DIM   256
#define K_CODES 1024
#define NQ      2
#define VQ_CAP  4096
#define VQ_MARGIN 2.0f

// ---------------- scratch (static device globals; no allocations) ----------
__device__ float g_h1[(size_t)NROWS * H_DIM];
__device__ float g_h2[(size_t)NROWS * H_DIM];
__device__ float g_z [(size_t)NROWS * D_DIM];
__device__ float g_r [(size_t)NROWS * D_DIM];
__device__ float g_q [(size_t)NROWS * D_DIM];
__device__ float g_dec[(size_t)NROWS * IN_DIM];
__device__ int    g_idx[NROWS * NQ];
__device__ float  g_cn[NQ * K_CODES];
__device__ double g_vq_sum;
__device__ double g_enc_sum;

// ---------------- helpers ----------------------------------------------------
__device__ __forceinline__ unsigned f2tf(float x) {
    unsigned u; asm("cvt.rna.tf32.f32 %0, %1;" : "=r"(u) : "f"(x)); return u;
}
__device__ __forceinline__ void mma_tf32(float c[4], const unsigned a[4], const unsigned b[2]) {
    asm volatile("mma.sync.aligned.m16n8k8.row.col.f32.tf32.tf32.f32 "
        "{%0,%1,%2,%3}, {%4,%5,%6,%7}, {%8,%9}, {%0,%1,%2,%3};"
        : "+f"(c[0]), "+f"(c[1]), "+f"(c[2]), "+f"(c[3])
        : "r"(a[0]), "r"(a[1]), "r"(a[2]), "r"(a[3]), "r"(b[0]), "r"(b[1]));
}
// order-preserving float<->uint maps (monotone, handles negatives)
__device__ __forceinline__ unsigned ordf(float f) {
    unsigned u = __float_as_uint(f);
    return (u >> 31) ? ~u : (u | 0x80000000u);
}
__device__ __forceinline__ float iordf(unsigned u) {
    return __uint_as_float((u >> 31) ? (u & 0x7FFFFFFFu) : ~u);
}

// ---------------- misc small kernels ---------------------------------------
__global__ void zero_acc_kernel() { g_vq_sum = 0.0; g_enc_sum = 0.0; }

__global__ void cnorm_kernel(const float* __restrict__ cbs) {
    int gw   = (blockIdx.x * blockDim.x + threadIdx.x) >> 5;
    int lane = threadIdx.x & 31;
    if (gw < NQ * K_CODES) {
        const float* row = cbs + (size_t)gw * D_DIM;
        float s = 0.f;
        #pragma unroll
        for (int e = 0; e < D_DIM / 32; e++) { float v = row[lane + 32 * e]; s += v * v; }
        #pragma unroll
        for (int o = 16; o > 0; o >>= 1) s += __shfl_xor_sync(0xffffffffu, s, o);
        if (lane == 0) g_cn[gw] = s;
    }
}

// ---------------- tensor-core GEMM: C = act(A @ B + bias) -------------------
// BK=8 double-buffered smem pipeline. BM=BN=128, 256 thr, 8 warps as 2x4,
// warp tile 64x32, mma m16n8k8 tf32. PR=true: 3-term split-tf32.
// K must be a multiple of 8 (56, 256, 512 all are).
template<bool PR, bool RELU>
__global__ __launch_bounds__(256, 2)
void gemm_tc(const float* __restrict__ A, const float* __restrict__ B,
             const float* __restrict__ bias, float* __restrict__ C,
             int N, int K)
{
    __shared__ float Ah[2][128][12];
    __shared__ float Al[PR ? 2 : 1][PR ? 128 : 1][PR ? 12 : 1];
    __shared__ float Bh[2][8][136];
    __shared__ float Bl[PR ? 2 : 1][PR ? 8 : 1][PR ? 136 : 1];

    const int tid  = threadIdx.x;
    const int lane = tid & 31, warp = tid >> 5;
    const int g = lane >> 2, t = lane & 3;
    const int wm = warp >> 2, wn = warp & 3;
    const int m0 = blockIdx.y * 128, n0 = blockIdx.x * 128;

    const int ar = tid >> 1, aq = (tid & 1) * 4;   // A: 128 rows x 8 cols
    const int bk = warp,     bq = lane * 4;        // B: 8 rows x 128 cols

    float c[4][4][4] = {};

    // prologue: load + convert + store k0 = 0 into buffer 0
    float4 va = *(const float4*)(A + (size_t)(m0 + ar) * K + aq);
    float4 vb = (n0 + bq < N) ? *(const float4*)(B + (size_t)bk * N + n0 + bq)
                              : make_float4(0.f, 0.f, 0.f, 0.f);
    {
        float av[4] = {va.x, va.y, va.z, va.w};
        float bv[4] = {vb.x, vb.y, vb.z, vb.w};
        #pragma unroll
        for (int j = 0; j < 4; j++) {
            unsigned h = f2tf(av[j]);
            Ah[0][ar][aq + j] = __uint_as_float(h);
            if constexpr (PR) Al[0][ar][aq + j] = __uint_as_float(f2tf(av[j] - __uint_as_float(h)));
        }
        #pragma unroll
        for (int j = 0; j < 4; j++) {
            unsigned h = f2tf(bv[j]);
            Bh[0][bk][bq + j] = __uint_as_float(h);
            if constexpr (PR) Bl[0][bk][bq + j] = __uint_as_float(f2tf(bv[j] - __uint_as_float(h)));
        }
    }
    __syncthreads();

    for (int k0 = 0; k0 < K; k0 += 8) {
        const int cur = (k0 >> 3) & 1, nxt = cur ^ 1;
        const bool more = (k0 + 8 < K);

        if (more) {
            va = *(const float4*)(A + (size_t)(m0 + ar) * K + k0 + 8 + aq);
            vb = (n0 + bq < N) ? *(const float4*)(B + (size_t)(k0 + 8 + bk) * N + n0 + bq)
                               : make_float4(0.f, 0.f, 0.f, 0.f);
        }

        // compute current buffer (single k8 step)
        unsigned bh[4][2], bl[PR ? 4 : 1][2];
        #pragma unroll
        for (int j = 0; j < 4; j++) {
            int nb = wn * 32 + j * 8;
            bh[j][0] = __float_as_uint(Bh[cur][t    ][nb + g]);
            bh[j][1] = __float_as_uint(Bh[cur][t + 4][nb + g]);
            if constexpr (PR) {
                bl[j][0] = __float_as_uint(Bl[cur][t    ][nb + g]);
                bl[j][1] = __float_as_uint(Bl[cur][t + 4][nb + g]);
            }
        }
        #pragma unroll
        for (int i = 0; i < 4; i++) {
            int mb = wm * 64 + i * 16;
            unsigned ah[4], al[PR ? 4 : 1];
            ah[0] = __float_as_uint(Ah[cur][mb + g    ][t    ]);
            ah[1] = __float_as_uint(Ah[cur][mb + g + 8][t    ]);
            ah[2] = __float_as_uint(Ah[cur][mb + g    ][t + 4]);
            ah[3] = __float_as_uint(Ah[cur][mb + g + 8][t + 4]);
            if constexpr (PR) {
                al[0] = __float_as_uint(Al[cur][mb + g    ][t    ]);
                al[1] = __float_as_uint(Al[cur][mb + g + 8][t    ]);
                al[2] = __float_as_uint(Al[cur][mb + g    ][t + 4]);
                al[3] = __float_as_uint(Al[cur][mb + g + 8][t + 4]);
            }
            #pragma unroll
            for (int j = 0; j < 4; j++) {
                mma_tf32(c[i][j], ah, bh[j]);
                if constexpr (PR) {
                    mma_tf32(c[i][j], ah, bl[j]);
                    mma_tf32(c[i][j], al, bh[j]);
                }
            }
        }

        // store next tile into the other buffer (overlaps the reads above)
        if (more) {
            float av[4] = {va.x, va.y, va.z, va.w};
            float bv[4] = {vb.x, vb.y, vb.z, vb.w};
            #pragma unroll
            for (int j = 0; j < 4; j++) {
                unsigned h = f2tf(av[j]);
                Ah[nxt][ar][aq + j] = __uint_as_float(h);
                if constexpr (PR) Al[nxt][ar][aq + j] = __uint_as_float(f2tf(av[j] - __uint_as_float(h)));
            }
            #pragma unroll
            for (int j = 0; j < 4; j++) {
                unsigned h = f2tf(bv[j]);
                Bh[nxt][bk][bq + j] = __uint_as_float(h);
                if constexpr (PR) Bl[nxt][bk][bq + j] = __uint_as_float(f2tf(bv[j] - __uint_as_float(h)));
            }
        }
        __syncthreads();
    }

    #pragma unroll
    for (int j = 0; j < 4; j++) {
        int col0 = n0 + wn * 32 + j * 8 + t * 2;
        float b0 = (col0     < N) ? bias[col0]     : 0.f;
        float b1 = (col0 + 1 < N) ? bias[col0 + 1] : 0.f;
        #pragma unroll
        for (int i = 0; i < 4; i++) {
            int row0 = m0 + wm * 64 + i * 16 + g;
            float v00 = c[i][j][0] + b0, v01 = c[i][j][1] + b1;
            float v10 = c[i][j][2] + b0, v11 = c[i][j][3] + b1;
            if (RELU) {
                v00 = fmaxf(v00, 0.f); v01 = fmaxf(v01, 0.f);
                v10 = fmaxf(v10, 0.f); v11 = fmaxf(v11, 0.f);
            }
            if (col0 < N) {
                C[(size_t)row0 * N + col0]       = v00;
                C[(size_t)(row0 + 8) * N + col0] = v10;
            }
            if (col0 + 1 < N) {
                C[(size_t)row0 * N + col0 + 1]       = v01;
                C[(size_t)(row0 + 8) * N + col0 + 1] = v11;
            }
        }
    }
}

// ---------------- VQ: tf32 approx scores + exact fp32 algebraic rescore -----
// Same BK=8 double-buffered pipeline for the distance GEMM.
__global__ __launch_bounds__(256, 2)
void vq_tc(const float* __restrict__ R, const float* __restrict__ cb,
           int qoff, float* __restrict__ code_out)
{
    __shared__ float Ah[2][128][12];
    __shared__ float Bh[2][8][136];
    __shared__ float cns[K_CODES];
    __shared__ float rnrow[128];
    __shared__ unsigned rowminU[128];
    __shared__ unsigned long long rowbest[128];
    __shared__ int cand[VQ_CAP];
    __shared__ int ncand;
    __shared__ float red[256];

    const int tid  = threadIdx.x;
    const int lane = tid & 31, warp = tid >> 5;
    const int g = lane >> 2, t = lane & 3;
    const int wm = warp >> 2, wn = warp & 3;
    const int m0 = blockIdx.x * 128;

    const int ar = tid >> 1, aq = (tid & 1) * 4;      // A(R): 128 x 8
    const int nloc = tid >> 1, kq2 = (tid & 1) * 4;   // B(codebook): transpose loader

    if (tid < 128) { rowminU[tid] = 0xFFFFFFFFu; rowbest[tid] = ~0ull; }
    if (tid == 0) ncand = 0;
    const float* cn = g_cn + qoff * K_CODES;
    #pragma unroll
    for (int i = tid; i < K_CODES; i += 256) cns[i] = cn[i];

    // per-row ||r||^2 (fp32), one warp per 16 rows
    for (int r = warp; r < 128; r += 8) {
        const float* rr = R + (size_t)(m0 + r) * D_DIM;
        float s = 0.f;
        #pragma unroll
        for (int e = 0; e < 8; e++) { float v = rr[lane + 32 * e]; s = fmaf(v, v, s); }
        #pragma unroll
        for (int o = 16; o > 0; o >>= 1) s += __shfl_xor_sync(0xffffffffu, s, o);
        if (lane == 0) rnrow[r] = s;
    }
    __syncthreads();

    for (int c0 = 0; c0 < K_CODES; c0 += 128) {
        float c[4][4][4] = {};

        // prologue: k0 = 0 into buffer 0
        float4 va = *(const float4*)(R + (size_t)(m0 + ar) * D_DIM + aq);
        float4 vb = *(const float4*)(cb + (size_t)(c0 + nloc) * D_DIM + kq2);
        {
            float av[4] = {va.x, va.y, va.z, va.w};
            float bv[4] = {vb.x, vb.y, vb.z, vb.w};
            #pragma unroll
            for (int j = 0; j < 4; j++) Ah[0][ar][aq + j] = __uint_as_float(f2tf(av[j]));
            #pragma unroll
            for (int j = 0; j < 4; j++) Bh[0][kq2 + j][nloc] = __uint_as_float(f2tf(bv[j]));
        }
        __syncthreads();

        for (int k0 = 0; k0 < D_DIM; k0 += 8) {
            const int cur = (k0 >> 3) & 1, nxt = cur ^ 1;
            const bool more = (k0 + 8 < D_DIM);

            if (more) {
                va = *(const float4*)(R + (size_t)(m0 + ar) * D_DIM + k0 + 8 + aq);
                vb = *(const float4*)(cb + (size_t)(c0 + nloc) * D_DIM + k0 + 8 + kq2);
            }

            unsigned bh[4][2];
            #pragma unroll
            for (int j = 0; j < 4; j++) {
                int nb = wn * 32 + j * 8;
                bh[j][0] = __float_as_uint(Bh[cur][t    ][nb + g]);
                bh[j][1] = __float_as_uint(Bh[cur][t + 4][nb + g]);
            }
            #pragma unroll
            for (int i = 0; i < 4; i++) {
                int mb = wm * 64 + i * 16;
                unsigned ah[4];
                ah[0] = __float_as_uint(Ah[cur][mb + g    ][t    ]);
                ah[1] = __float_as_uint(Ah[cur][mb + g + 8][t    ]);
                ah[2] = __float_as_uint(Ah[cur][mb + g    ][t + 4]);
                ah[3] = __float_as_uint(Ah[cur][mb + g + 8][t + 4]);
                #pragma unroll
                for (int j = 0; j < 4; j++) mma_tf32(c[i][j], ah, bh[j]);
            }

            if (more) {
                float av[4] = {va.x, va.y, va.z, va.w};
                float bv[4] = {vb.x, vb.y, vb.z, vb.w};
                #pragma unroll
                for (int j = 0; j < 4; j++) Ah[nxt][ar][aq + j] = __uint_as_float(f2tf(av[j]));
                #pragma unroll
                for (int j = 0; j < 4; j++) Bh[nxt][kq2 + j][nloc] = __uint_as_float(f2tf(bv[j]));
            }
            __syncthreads();
        }

        // approx scores -> running row minima
        float smin[8];
        #pragma unroll
        for (int s = 0; s < 8; s++) smin[s] = FLT_MAX;
        #pragma unroll
        for (int i = 0; i < 4; i++)
            #pragma unroll
            for (int j = 0; j < 4; j++) {
                int cA = c0 + wn * 32 + j * 8 + t * 2;
                float cn0 = cns[cA], cn1 = cns[cA + 1];
                float s00 = fmaf(-2.f, c[i][j][0], cn0);
                float s01 = fmaf(-2.f, c[i][j][1], cn1);
                float s10 = fmaf(-2.f, c[i][j][2], cn0);
                float s11 = fmaf(-2.f, c[i][j][3], cn1);
                smin[2*i]   = fminf(smin[2*i],   fminf(s00, s01));
                smin[2*i+1] = fminf(smin[2*i+1], fminf(s10, s11));
            }
        #pragma unroll
        for (int i = 0; i < 4; i++) {
            int r0 = wm * 64 + i * 16 + g;
            atomicMin(&rowminU[r0],     ordf(smin[2*i]));
            atomicMin(&rowminU[r0 + 8], ordf(smin[2*i+1]));
        }
        __syncthreads();

        // candidate collection (running min >= final min => complete superset)
        #pragma unroll
        for (int i = 0; i < 4; i++) {
            int r0 = wm * 64 + i * 16 + g;
            float th0 = iordf(rowminU[r0])     + VQ_MARGIN;
            float th1 = iordf(rowminU[r0 + 8]) + VQ_MARGIN;
            #pragma unroll
            for (int j = 0; j < 4; j++) {
                int cA = c0 + wn * 32 + j * 8 + t * 2;
                float cn0 = cns[cA], cn1 = cns[cA + 1];
                float s00 = fmaf(-2.f, c[i][j][0], cn0);
                float s01 = fmaf(-2.f, c[i][j][1], cn1);
                float s10 = fmaf(-2.f, c[i][j][2], cn0);
                float s11 = fmaf(-2.f, c[i][j][3], cn1);
                if (s00 <= th0) { int p = atomicAdd(&ncand, 1); if (p < VQ_CAP) cand[p] = (r0 << 10) | cA; }
                if (s01 <= th0) { int p = atomicAdd(&ncand, 1); if (p < VQ_CAP) cand[p] = (r0 << 10) | (cA + 1); }
                if (s10 <= th1) { int p = atomicAdd(&ncand, 1); if (p < VQ_CAP) cand[p] = ((r0 + 8) << 10) | cA; }
                if (s11 <= th1) { int p = atomicAdd(&ncand, 1); if (p < VQ_CAP) cand[p] = ((r0 + 8) << 10) | (cA + 1); }
            }
        }
        __syncthreads();
    }

    // exact fp32 rescore, algebraic form (matches reference): s = ||c||^2 - 2 r.c
    int nc = min(ncand, VQ_CAP);
    for (int ci = warp; ci < nc; ci += 8) {
        int pk = cand[ci];
        int lr = pk >> 10, code = pk & 1023;
        const float* rr = R  + (size_t)(m0 + lr) * D_DIM;
        const float* cc = cb + (size_t)code * D_DIM;
        float acc = 0.f;
        #pragma unroll
        for (int e = 0; e < 8; e++) acc = fmaf(rr[lane + e * 32], cc[lane + e * 32], acc);
        #pragma unroll
        for (int o = 16; o > 0; o >>= 1) acc += __shfl_xor_sync(0xffffffffu, acc, o);
        if (lane == 0) {
            float s = fmaf(-2.f, acc, cns[code]);
            atomicMin(&rowbest[lr],
                      ((unsigned long long)ordf(s) << 32) | (unsigned)code);
        }
    }
    __syncthreads();

    float dist = 0.f;
    if (tid < 128) {
        unsigned long long b = rowbest[tid];
        int code = (int)(b & 0xFFFFFFFFu);
        dist = iordf((unsigned)(b >> 32)) + rnrow[tid];
        int n = m0 + tid;
        g_idx[n * NQ + qoff] = code;
        code_out[(size_t)n * NQ] = (float)code;
    }
    red[tid] = dist;
    __syncthreads();
    for (int s = 128; s > 0; s >>= 1) {
        if (tid < s) red[tid] += red[tid + s];
        __syncthreads();
    }
    if (tid == 0) atomicAdd(&g_vq_sum, (double)red[0]);
}

// ---------------- gathers ----------------------------------------------------
__global__ void gather_residual(const float* __restrict__ z, const float* __restrict__ cb0) {
    int n = blockIdx.x, e = threadIdx.x;
    int c = g_idx[n * NQ + 0];
    float zv = z[(size_t)n * D_DIM + e];
    float cv = cb0[(size_t)c * D_DIM + e];
    g_r[(size_t)n * D_DIM + e] = zv - cv;
    g_q[(size_t)n * D_DIM + e] = cv;
}
__global__ void gather_add(const float* __restrict__ cb1) {
    int n = blockIdx.x, e = threadIdx.x;
    int c = g_idx[n * NQ + 1];
    g_q[(size_t)n * D_DIM + e] += cb1[(size_t)c * D_DIM + e];
}

// ---------------- L1 reduction -----------------------------------------------
__global__ void l1_kernel(const float* __restrict__ x) {
    const size_t TOT = (size_t)NROWS * IN_DIM;
    float s = 0.f;
    for (size_t i = (size_t)blockIdx.x * blockDim.x + threadIdx.x; i < TOT;
         i += (size_t)gridDim.x * blockDim.x)
        s += fabsf(x[i] - g_dec[i]);
    __shared__ float red[256];
    red[threadIdx.x] = s;
    __syncthreads();
    for (int o = 128; o > 0; o >>= 1) {
        if (threadIdx.x < o) red[threadIdx.x] += red[threadIdx.x + o];
        __syncthreads();
    }
    if (threadIdx.x == 0) atomicAdd(&g_enc_sum, (double)red[0]);
}

// ---------------- finalize ---------------------------------------------------
__global__ void finalize_kernel(float* out, int write_loss) {
    if (write_loss) {
        double enc = g_enc_sum / ((double)NROWS * IN_DIM);
        double vq  = g_vq_sum  / ((double)NROWS * D_DIM);
        out[0] = (float)(enc + 5.0 * vq);
    }
}

// ---------------- launch -----------------------------------------------------
extern "C" void kernel_launch(void* const* d_in, const int* in_sizes, int n_in,
                              void* d_out, int out_size)
{
    const float* state = (const float*)d_in[0];
    const float* ew1 = (const float*)d_in[1];  const float* eb1 = (const float*)d_in[2];
    const float* ew2 = (const float*)d_in[3];  const float* eb2 = (const float*)d_in[4];
    const float* ew3 = (const float*)d_in[5];  const float* eb3 = (const float*)d_in[6];
    const float* dw1 = (const float*)d_in[7];  const float* db1 = (const float*)d_in[8];
    const float* dw2 = (const float*)d_in[9];  const float* db2 = (const float*)d_in[10];
    const float* dw3 = (const float*)d_in[11]; const float* db3 = (const float*)d_in[12];
    const float* cbs = (const float*)d_in[13];

    float* out = (float*)d_out;
    int code_base = out_size - NROWS * NQ;
    if (code_base < 0) code_base = 0;
    float* codes = out + code_base;

    float *p_h1, *p_h2, *p_z, *p_r, *p_q, *p_dec;
    cudaGetSymbolAddress((void**)&p_h1,  g_h1);
    cudaGetSymbolAddress((void**)&p_h2,  g_h2);
    cudaGetSymbolAddress((void**)&p_z,   g_z);
    cudaGetSymbolAddress((void**)&p_r,   g_r);
    cudaGetSymbolAddress((void**)&p_q,   g_q);
    cudaGetSymbolAddress((void**)&p_dec, g_dec);

    const int MB = NROWS / 128;

    zero_acc_kernel<<<1, 1>>>();
    cnorm_kernel<<<(NQ * K_CODES * 32) / 256, 256>>>(cbs);

    // encoder: 3-term split-tf32 (fp32-class accuracy protects argmin)
    gemm_tc<true, true ><<<dim3(H_DIM / 128, MB), 256>>>(state, ew1, eb1, p_h1, H_DIM, IN_DIM);
    gemm_tc<true, true ><<<dim3(H_DIM / 128, MB), 256>>>(p_h1,  ew2, eb2, p_h2, H_DIM, H_DIM);
    gemm_tc<true, false><<<dim3(D_DIM / 128, MB), 256>>>(p_h2,  ew3, eb3, p_z,  D_DIM, H_DIM);

    // residual VQ: approx tf32 scores + exact fp32 rescore
    vq_tc<<<MB, 256>>>(p_z, cbs, 0, codes + 0);
    gather_residual<<<NROWS, D_DIM>>>(p_z, cbs);
    vq_tc<<<MB, 256>>>(p_r, cbs + (size_t)K_CODES * D_DIM, 1, codes + 1);
    gather_add<<<NROWS, D_DIM>>>(cbs + (size_t)K_CODES * D_DIM);

    // decoder: plain tf32 (L1-mean averages out tf32 noise)
    gemm_tc<false, true ><<<dim3(H_DIM / 128, MB), 256>>>(p_q,  dw1, db1, p_h1, H_DIM, D_DIM);
    gemm_tc<false, true ><<<dim3(H_DIM / 128, MB), 256>>>(p_h1, dw2, db2, p_h2, H_DIM, H_DIM);
    gemm_tc<false, false><<<dim3(1, MB),           256>>>(p_h2, dw3, db3, p_dec, IN_DIM, H_DIM);
    l1_kernel<<<1024, 256>>>(state);

    finalize_kernel<<<1, 1>>>(out, code_base >= 1);
}

// round 17
// speedup vs baseline: 2.1297x; 1.0040x over previous
#include <cuda_runtime.h>
#include <math.h>
#include <float.h>

#define NROWS   131072
#define IN_DIM  56
#define H_DIM   512
#define D_DIM   256
#define K_CODES 1024
#define NQ      2
#define VQ_CAP  4096
#define VQ_MARGIN 2.0f

// ---------------- scratch (static device globals; no allocations) ----------
__device__ float g_h1[(size_t)NROWS * H_DIM];
__device__ float g_h2[(size_t)NROWS * H_DIM];
__device__ float g_z [(size_t)NROWS * D_DIM];
__device__ float g_r [(size_t)NROWS * D_DIM];
__device__ float g_q [(size_t)NROWS * D_DIM];
__device__ float g_dec[(size_t)NROWS * IN_DIM];
__device__ int    g_idx[NROWS * NQ];
__device__ float  g_cn[NQ * K_CODES];
__device__ double g_vq_sum;
__device__ double g_enc_sum;

// ---------------- helpers ----------------------------------------------------
__device__ __forceinline__ unsigned f2tf(float x) {
    unsigned u; asm("cvt.rna.tf32.f32 %0, %1;" : "=r"(u) : "f"(x)); return u;
}
__device__ __forceinline__ void mma_tf32(float c[4], const unsigned a[4], const unsigned b[2]) {
    asm volatile("mma.sync.aligned.m16n8k8.row.col.f32.tf32.tf32.f32 "
        "{%0,%1,%2,%3}, {%4,%5,%6,%7}, {%8,%9}, {%0,%1,%2,%3};"
        : "+f"(c[0]), "+f"(c[1]), "+f"(c[2]), "+f"(c[3])
        : "r"(a[0]), "r"(a[1]), "r"(a[2]), "r"(a[3]), "r"(b[0]), "r"(b[1]));
}
// order-preserving float<->uint maps (monotone, handles negatives)
__device__ __forceinline__ unsigned ordf(float f) {
    unsigned u = __float_as_uint(f);
    return (u >> 31) ? ~u : (u | 0x80000000u);
}
__device__ __forceinline__ float iordf(unsigned u) {
    return __uint_as_float((u >> 31) ? (u & 0x7FFFFFFFu) : ~u);
}

// ---------------- misc small kernels ---------------------------------------
__global__ void zero_acc_kernel() { g_vq_sum = 0.0; g_enc_sum = 0.0; }

__global__ void cnorm_kernel(const float* __restrict__ cbs) {
    int gw   = (blockIdx.x * blockDim.x + threadIdx.x) >> 5;
    int lane = threadIdx.x & 31;
    if (gw < NQ * K_CODES) {
        const float* row = cbs + (size_t)gw * D_DIM;
        float s = 0.f;
        #pragma unroll
        for (int e = 0; e < D_DIM / 32; e++) { float v = row[lane + 32 * e]; s += v * v; }
        #pragma unroll
        for (int o = 16; o > 0; o >>= 1) s += __shfl_xor_sync(0xffffffffu, s, o);
        if (lane == 0) g_cn[gw] = s;
    }
}

// ---------------- tensor-core GEMM: C = act(A @ B + bias) -------------------
// BK=8 double-buffered smem pipeline. BM=BN=128, 256 thr, 8 warps as 2x4,
// warp tile 64x32, mma m16n8k8 tf32. PR=true: 3-term split-tf32 with
// dependency-broken issue order (hh sweep, hl sweep, lh sweep per i —
// per-accumulator order unchanged => bit-identical).
template<bool PR, bool RELU>
__global__ __launch_bounds__(256, 2)
void gemm_tc(const float* __restrict__ A, const float* __restrict__ B,
             const float* __restrict__ bias, float* __restrict__ C,
             int N, int K)
{
    __shared__ float Ah[2][128][12];
    __shared__ float Al[PR ? 2 : 1][PR ? 128 : 1][PR ? 12 : 1];
    __shared__ float Bh[2][8][136];
    __shared__ float Bl[PR ? 2 : 1][PR ? 8 : 1][PR ? 136 : 1];

    const int tid  = threadIdx.x;
    const int lane = tid & 31, warp = tid >> 5;
    const int g = lane >> 2, t = lane & 3;
    const int wm = warp >> 2, wn = warp & 3;
    const int m0 = blockIdx.y * 128, n0 = blockIdx.x * 128;

    const int ar = tid >> 1, aq = (tid & 1) * 4;   // A: 128 rows x 8 cols
    const int bk = warp,     bq = lane * 4;        // B: 8 rows x 128 cols

    float c[4][4][4] = {};

    // prologue: load + convert + store k0 = 0 into buffer 0
    float4 va = *(const float4*)(A + (size_t)(m0 + ar) * K + aq);
    float4 vb = (n0 + bq < N) ? *(const float4*)(B + (size_t)bk * N + n0 + bq)
                              : make_float4(0.f, 0.f, 0.f, 0.f);
    {
        float av[4] = {va.x, va.y, va.z, va.w};
        float bv[4] = {vb.x, vb.y, vb.z, vb.w};
        #pragma unroll
        for (int j = 0; j < 4; j++) {
            unsigned h = f2tf(av[j]);
            Ah[0][ar][aq + j] = __uint_as_float(h);
            if constexpr (PR) Al[0][ar][aq + j] = __uint_as_float(f2tf(av[j] - __uint_as_float(h)));
        }
        #pragma unroll
        for (int j = 0; j < 4; j++) {
            unsigned h = f2tf(bv[j]);
            Bh[0][bk][bq + j] = __uint_as_float(h);
            if constexpr (PR) Bl[0][bk][bq + j] = __uint_as_float(f2tf(bv[j] - __uint_as_float(h)));
        }
    }
    __syncthreads();

    for (int k0 = 0; k0 < K; k0 += 8) {
        const int cur = (k0 >> 3) & 1, nxt = cur ^ 1;
        const bool more = (k0 + 8 < K);

        if (more) {
            va = *(const float4*)(A + (size_t)(m0 + ar) * K + k0 + 8 + aq);
            vb = (n0 + bq < N) ? *(const float4*)(B + (size_t)(k0 + 8 + bk) * N + n0 + bq)
                               : make_float4(0.f, 0.f, 0.f, 0.f);
        }

        // compute current buffer (single k8 step)
        unsigned bh[4][2], bl[PR ? 4 : 1][2];
        #pragma unroll
        for (int j = 0; j < 4; j++) {
            int nb = wn * 32 + j * 8;
            bh[j][0] = __float_as_uint(Bh[cur][t    ][nb + g]);
            bh[j][1] = __float_as_uint(Bh[cur][t + 4][nb + g]);
            if constexpr (PR) {
                bl[j][0] = __float_as_uint(Bl[cur][t    ][nb + g]);
                bl[j][1] = __float_as_uint(Bl[cur][t + 4][nb + g]);
            }
        }
        #pragma unroll
        for (int i = 0; i < 4; i++) {
            int mb = wm * 64 + i * 16;
            unsigned ah[4], al[PR ? 4 : 1];
            ah[0] = __float_as_uint(Ah[cur][mb + g    ][t    ]);
            ah[1] = __float_as_uint(Ah[cur][mb + g + 8][t    ]);
            ah[2] = __float_as_uint(Ah[cur][mb + g    ][t + 4]);
            ah[3] = __float_as_uint(Ah[cur][mb + g + 8][t + 4]);
            if constexpr (PR) {
                al[0] = __float_as_uint(Al[cur][mb + g    ][t    ]);
                al[1] = __float_as_uint(Al[cur][mb + g + 8][t    ]);
                al[2] = __float_as_uint(Al[cur][mb + g    ][t + 4]);
                al[3] = __float_as_uint(Al[cur][mb + g + 8][t + 4]);
            }
            // dependency-broken issue: three j-sweeps; consecutive MMAs hit
            // different accumulators; per-accumulator order stays hh->hl->lh.
            #pragma unroll
            for (int j = 0; j < 4; j++) mma_tf32(c[i][j], ah, bh[j]);
            if constexpr (PR) {
                #pragma unroll
                for (int j = 0; j < 4; j++) mma_tf32(c[i][j], ah, bl[j]);
                #pragma unroll
                for (int j = 0; j < 4; j++) mma_tf32(c[i][j], al, bh[j]);
            }
        }

        // store next tile into the other buffer (overlaps the reads above)
        if (more) {
            float av[4] = {va.x, va.y, va.z, va.w};
            float bv[4] = {vb.x, vb.y, vb.z, vb.w};
            #pragma unroll
            for (int j = 0; j < 4; j++) {
                unsigned h = f2tf(av[j]);
                Ah[nxt][ar][aq + j] = __uint_as_float(h);
                if constexpr (PR) Al[nxt][ar][aq + j] = __uint_as_float(f2tf(av[j] - __uint_as_float(h)));
            }
            #pragma unroll
            for (int j = 0; j < 4; j++) {
                unsigned h = f2tf(bv[j]);
                Bh[nxt][bk][bq + j] = __uint_as_float(h);
                if constexpr (PR) Bl[nxt][bk][bq + j] = __uint_as_float(f2tf(bv[j] - __uint_as_float(h)));
            }
        }
        __syncthreads();
    }

    #pragma unroll
    for (int j = 0; j < 4; j++) {
        int col0 = n0 + wn * 32 + j * 8 + t * 2;
        float b0 = (col0     < N) ? bias[col0]     : 0.f;
        float b1 = (col0 + 1 < N) ? bias[col0 + 1] : 0.f;
        #pragma unroll
        for (int i = 0; i < 4; i++) {
            int row0 = m0 + wm * 64 + i * 16 + g;
            float v00 = c[i][j][0] + b0, v01 = c[i][j][1] + b1;
            float v10 = c[i][j][2] + b0, v11 = c[i][j][3] + b1;
            if (RELU) {
                v00 = fmaxf(v00, 0.f); v01 = fmaxf(v01, 0.f);
                v10 = fmaxf(v10, 0.f); v11 = fmaxf(v11, 0.f);
            }
            if (col0 < N) {
                C[(size_t)row0 * N + col0]       = v00;
                C[(size_t)(row0 + 8) * N + col0] = v10;
            }
            if (col0 + 1 < N) {
                C[(size_t)row0 * N + col0 + 1]       = v01;
                C[(size_t)(row0 + 8) * N + col0 + 1] = v11;
            }
        }
    }
}

// ---------------- VQ: tf32 approx scores + exact fp32 algebraic rescore -----
// Same BK=8 double-buffered pipeline for the distance GEMM (non-PR: already
// dependency-spaced).
__global__ __launch_bounds__(256, 2)
void vq_tc(const float* __restrict__ R, const float* __restrict__ cb,
           int qoff, float* __restrict__ code_out)
{
    __shared__ float Ah[2][128][12];
    __shared__ float Bh[2][8][136];
    __shared__ float cns[K_CODES];
    __shared__ float rnrow[128];
    __shared__ unsigned rowminU[128];
    __shared__ unsigned long long rowbest[128];
    __shared__ int cand[VQ_CAP];
    __shared__ int ncand;
    __shared__ float red[256];

    const int tid  = threadIdx.x;
    const int lane = tid & 31, warp = tid >> 5;
    const int g = lane >> 2, t = lane & 3;
    const int wm = warp >> 2, wn = warp & 3;
    const int m0 = blockIdx.x * 128;

    const int ar = tid >> 1, aq = (tid & 1) * 4;      // A(R): 128 x 8
    const int nloc = tid >> 1, kq2 = (tid & 1) * 4;   // B(codebook): transpose loader

    if (tid < 128) { rowminU[tid] = 0xFFFFFFFFu; rowbest[tid] = ~0ull; }
    if (tid == 0) ncand = 0;
    const float* cn = g_cn + qoff * K_CODES;
    #pragma unroll
    for (int i = tid; i < K_CODES; i += 256) cns[i] = cn[i];

    // per-row ||r||^2 (fp32), one warp per 16 rows
    for (int r = warp; r < 128; r += 8) {
        const float* rr = R + (size_t)(m0 + r) * D_DIM;
        float s = 0.f;
        #pragma unroll
        for (int e = 0; e < 8; e++) { float v = rr[lane + 32 * e]; s = fmaf(v, v, s); }
        #pragma unroll
        for (int o = 16; o > 0; o >>= 1) s += __shfl_xor_sync(0xffffffffu, s, o);
        if (lane == 0) rnrow[r] = s;
    }
    __syncthreads();

    for (int c0 = 0; c0 < K_CODES; c0 += 128) {
        float c[4][4][4] = {};

        // prologue: k0 = 0 into buffer 0
        float4 va = *(const float4*)(R + (size_t)(m0 + ar) * D_DIM + aq);
        float4 vb = *(const float4*)(cb + (size_t)(c0 + nloc) * D_DIM + kq2);
        {
            float av[4] = {va.x, va.y, va.z, va.w};
            float bv[4] = {vb.x, vb.y, vb.z, vb.w};
            #pragma unroll
            for (int j = 0; j < 4; j++) Ah[0][ar][aq + j] = __uint_as_float(f2tf(av[j]));
            #pragma unroll
            for (int j = 0; j < 4; j++) Bh[0][kq2 + j][nloc] = __uint_as_float(f2tf(bv[j]));
        }
        __syncthreads();

        for (int k0 = 0; k0 < D_DIM; k0 += 8) {
            const int cur = (k0 >> 3) & 1, nxt = cur ^ 1;
            const bool more = (k0 + 8 < D_DIM);

            if (more) {
                va = *(const float4*)(R + (size_t)(m0 + ar) * D_DIM + k0 + 8 + aq);
                vb = *(const float4*)(cb + (size_t)(c0 + nloc) * D_DIM + k0 + 8 + kq2);
            }

            unsigned bh[4][2];
            #pragma unroll
            for (int j = 0; j < 4; j++) {
                int nb = wn * 32 + j * 8;
                bh[j][0] = __float_as_uint(Bh[cur][t    ][nb + g]);
                bh[j][1] = __float_as_uint(Bh[cur][t + 4][nb + g]);
            }
            #pragma unroll
            for (int i = 0; i < 4; i++) {
                int mb = wm * 64 + i * 16;
                unsigned ah[4];
                ah[0] = __float_as_uint(Ah[cur][mb + g    ][t    ]);
                ah[1] = __float_as_uint(Ah[cur][mb + g + 8][t    ]);
                ah[2] = __float_as_uint(Ah[cur][mb + g    ][t + 4]);
                ah[3] = __float_as_uint(Ah[cur][mb + g + 8][t + 4]);
                #pragma unroll
                for (int j = 0; j < 4; j++) mma_tf32(c[i][j], ah, bh[j]);
            }

            if (more) {
                float av[4] = {va.x, va.y, va.z, va.w};
                float bv[4] = {vb.x, vb.y, vb.z, vb.w};
                #pragma unroll
                for (int j = 0; j < 4; j++) Ah[nxt][ar][aq + j] = __uint_as_float(f2tf(av[j]));
                #pragma unroll
                for (int j = 0; j < 4; j++) Bh[nxt][kq2 + j][nloc] = __uint_as_float(f2tf(bv[j]));
            }
            __syncthreads();
        }

        // approx scores -> running row minima
        float smin[8];
        #pragma unroll
        for (int s = 0; s < 8; s++) smin[s] = FLT_MAX;
        #pragma unroll
        for (int i = 0; i < 4; i++)
            #pragma unroll
            for (int j = 0; j < 4; j++) {
                int cA = c0 + wn * 32 + j * 8 + t * 2;
                float cn0 = cns[cA], cn1 = cns[cA + 1];
                float s00 = fmaf(-2.f, c[i][j][0], cn0);
                float s01 = fmaf(-2.f, c[i][j][1], cn1);
                float s10 = fmaf(-2.f, c[i][j][2], cn0);
                float s11 = fmaf(-2.f, c[i][j][3], cn1);
                smin[2*i]   = fminf(smin[2*i],   fminf(s00, s01));
                smin[2*i+1] = fminf(smin[2*i+1], fminf(s10, s11));
            }
        #pragma unroll
        for (int i = 0; i < 4; i++) {
            int r0 = wm * 64 + i * 16 + g;
            atomicMin(&rowminU[r0],     ordf(smin[2*i]));
            atomicMin(&rowminU[r0 + 8], ordf(smin[2*i+1]));
        }
        __syncthreads();

        // candidate collection (running min >= final min => complete superset)
        #pragma unroll
        for (int i = 0; i < 4; i++) {
            int r0 = wm * 64 + i * 16 + g;
            float th0 = iordf(rowminU[r0])     + VQ_MARGIN;
            float th1 = iordf(rowminU[r0 + 8]) + VQ_MARGIN;
            #pragma unroll
            for (int j = 0; j < 4; j++) {
                int cA = c0 + wn * 32 + j * 8 + t * 2;
                float cn0 = cns[cA], cn1 = cns[cA + 1];
                float s00 = fmaf(-2.f, c[i][j][0], cn0);
                float s01 = fmaf(-2.f, c[i][j][1], cn1);
                float s10 = fmaf(-2.f, c[i][j][2], cn0);
                float s11 = fmaf(-2.f, c[i][j][3], cn1);
                if (s00 <= th0) { int p = atomicAdd(&ncand, 1); if (p < VQ_CAP) cand[p] = (r0 << 10) | cA; }
                if (s01 <= th0) { int p = atomicAdd(&ncand, 1); if (p < VQ_CAP) cand[p] = (r0 << 10) | (cA + 1); }
                if (s10 <= th1) { int p = atomicAdd(&ncand, 1); if (p < VQ_CAP) cand[p] = ((r0 + 8) << 10) | cA; }
                if (s11 <= th1) { int p = atomicAdd(&ncand, 1); if (p < VQ_CAP) cand[p] = ((r0 + 8) << 10) | (cA + 1); }
            }
        }
        __syncthreads();
    }

    // exact fp32 rescore, algebraic form (matches reference): s = ||c||^2 - 2 r.c
    int nc = min(ncand, VQ_CAP);
    for (int ci = warp; ci < nc; ci += 8) {
        int pk = cand[ci];
        int lr = pk >> 10, code = pk & 1023;
        const float* rr = R  + (size_t)(m0 + lr) * D_DIM;
        const float* cc = cb + (size_t)code * D_DIM;
        float acc = 0.f;
        #pragma unroll
        for (int e = 0; e < 8; e++) acc = fmaf(rr[lane + e * 32], cc[lane + e * 32], acc);
        #pragma unroll
        for (int o = 16; o > 0; o >>= 1) acc += __shfl_xor_sync(0xffffffffu, acc, o);
        if (lane == 0) {
            float s = fmaf(-2.f, acc, cns[code]);
            atomicMin(&rowbest[lr],
                      ((unsigned long long)ordf(s) << 32) | (unsigned)code);
        }
    }
    __syncthreads();

    float dist = 0.f;
    if (tid < 128) {
        unsigned long long b = rowbest[tid];
        int code = (int)(b & 0xFFFFFFFFu);
        dist = iordf((unsigned)(b >> 32)) + rnrow[tid];
        int n = m0 + tid;
        g_idx[n * NQ + qoff] = code;
        code_out[(size_t)n * NQ] = (float)code;
    }
    red[tid] = dist;
    __syncthreads();
    for (int s = 128; s > 0; s >>= 1) {
        if (tid < s) red[tid] += red[tid + s];
        __syncthreads();
    }
    if (tid == 0) atomicAdd(&g_vq_sum, (double)red[0]);
}

// ---------------- gathers ----------------------------------------------------
__global__ void gather_residual(const float* __restrict__ z, const float* __restrict__ cb0) {
    int n = blockIdx.x, e = threadIdx.x;
    int c = g_idx[n * NQ + 0];
    float zv = z[(size_t)n * D_DIM + e];
    float cv = cb0[(size_t)c * D_DIM + e];
    g_r[(size_t)n * D_DIM + e] = zv - cv;
    g_q[(size_t)n * D_DIM + e] = cv;
}
__global__ void gather_add(const float* __restrict__ cb1) {
    int n = blockIdx.x, e = threadIdx.x;
    int c = g_idx[n * NQ + 1];
    g_q[(size_t)n * D_DIM + e] += cb1[(size_t)c * D_DIM + e];
}

// ---------------- L1 reduction -----------------------------------------------
__global__ void l1_kernel(const float* __restrict__ x) {
    const size_t TOT = (size_t)NROWS * IN_DIM;
    float s = 0.f;
    for (size_t i = (size_t)blockIdx.x * blockDim.x + threadIdx.x; i < TOT;
         i += (size_t)gridDim.x * blockDim.x)
        s += fabsf(x[i] - g_dec[i]);
    __shared__ float red[256];
    red[threadIdx.x] = s;
    __syncthreads();
    for (int o = 128; o > 0; o >>= 1) {
        if (threadIdx.x < o) red[threadIdx.x] += red[threadIdx.x + o];
        __syncthreads();
    }
    if (threadIdx.x == 0) atomicAdd(&g_enc_sum, (double)red[0]);
}

// ---------------- finalize ---------------------------------------------------
__global__ void finalize_kernel(float* out, int write_loss) {
    if (write_loss) {
        double enc = g_enc_sum / ((double)NROWS * IN_DIM);
        double vq  = g_vq_sum  / ((double)NROWS * D_DIM);
        out[0] = (float)(enc + 5.0 * vq);
    }
}

// ---------------- launch -----------------------------------------------------
extern "C" void kernel_launch(void* const* d_in, const int* in_sizes, int n_in,
                              void* d_out, int out_size)
{
    const float* state = (const float*)d_in[0];
    const float* ew1 = (const float*)d_in[1];  const float* eb1 = (const float*)d_in[2];
    const float* ew2 = (const float*)d_in[3];  const float* eb2 = (const float*)d_in[4];
    const float* ew3 = (const float*)d_in[5];  const float* eb3 = (const float*)d_in[6];
    const float* dw1 = (const float*)d_in[7];  const float* db1 = (const float*)d_in[8];
    const float* dw2 = (const float*)d_in[9];  const float* db2 = (const float*)d_in[10];
    const float* dw3 = (const float*)d_in[11]; const float* db3 = (const float*)d_in[12];
    const float* cbs = (const float*)d_in[13];

    float* out = (float*)d_out;
    int code_base = out_size - NROWS * NQ;
    if (code_base < 0) code_base = 0;
    float* codes = out + code_base;

    float *p_h1, *p_h2, *p_z, *p_r, *p_q, *p_dec;
    cudaGetSymbolAddress((void**)&p_h1,  g_h1);
    cudaGetSymbolAddress((void**)&p_h2,  g_h2);
    cudaGetSymbolAddress((void**)&p_z,   g_z);
    cudaGetSymbolAddress((void**)&p_r,   g_r);
    cudaGetSymbolAddress((void**)&p_q,   g_q);
    cudaGetSymbolAddress((void**)&p_dec, g_dec);

    const int MB = NROWS / 128;

    zero_acc_kernel<<<1, 1>>>();
    cnorm_kernel<<<(NQ * K_CODES * 32) / 256, 256>>>(cbs);

    // encoder: 3-term split-tf32 (fp32-class accuracy protects argmin)
    gemm_tc<true, true ><<<dim3(H_DIM / 128, MB), 256>>>(state, ew1, eb1, p_h1, H_DIM, IN_DIM);
    gemm_tc<true, true ><<<dim3(H_DIM / 128, MB), 256>>>(p_h1,  ew2, eb2, p_h2, H_DIM, H_DIM);
    gemm_tc<true, false><<<dim3(D_DIM / 128, MB), 256>>>(p_h2,  ew3, eb3, p_z,  D_DIM, H_DIM);

    // residual VQ: approx tf32 scores + exact fp32 rescore
    vq_tc<<<MB, 256>>>(p_z, cbs, 0, codes + 0);
    gather_residual<<<NROWS, D_DIM>>>(p_z, cbs);
    vq_tc<<<MB, 256>>>(p_r, cbs + (size_t)K_CODES * D_DIM, 1, codes + 1);
    gather_add<<<NROWS, D_DIM>>>(cbs + (size_t)K_CODES * D_DIM);

    // decoder: plain tf32 (L1-mean averages out tf32 noise)
    gemm_tc<false, true ><<<dim3(H_DIM / 128, MB), 256>>>(p_q,  dw1, db1, p_h1, H_DIM, D_DIM);
    gemm_tc<false, true ><<<dim3(H_DIM / 128, MB), 256>>>(p_h1, dw2, db2, p_h2, H_DIM, H_DIM);
    gemm_tc<false, false><<<dim3(1, MB),           256>>>(p_h2, dw3, db3, p_dec, IN_DIM, H_DIM);
    l1_kernel<<<1024, 256>>>(state);

    finalize_kernel<<<1, 1>>>(out, code_base >= 1);
}